// round 8
// baseline (speedup 1.0000x reference)
#include <cuda_runtime.h>
#include <cuda_bf16.h>
#include <stdint.h>

// Problem constants
#define Bv 4
#define Sv 2048
#define Dv 1024
#define Hv 16
#define HDv 64
#define Mv (Bv * Sv)   // 8192 rows

// ---------------------------------------------------------------------------
// PTX helpers (sm_80+ baseline: mma.sync / ldmatrix / cp.async)
// ---------------------------------------------------------------------------
__device__ __forceinline__ uint32_t smem_to_u32(const void* p) {
    uint32_t a;
    asm("{ .reg .u64 t; cvta.to.shared.u64 t, %1; cvt.u32.u64 %0, t; }"
        : "=r"(a) : "l"(p));
    return a;
}

__device__ __forceinline__ void mma_bf16(float* c, const uint32_t* a,
                                         uint32_t b0, uint32_t b1) {
    asm volatile(
        "mma.sync.aligned.m16n8k16.row.col.f32.bf16.bf16.f32 "
        "{%0,%1,%2,%3}, {%4,%5,%6,%7}, {%8,%9}, {%0,%1,%2,%3};\n"
        : "+f"(c[0]), "+f"(c[1]), "+f"(c[2]), "+f"(c[3])
        : "r"(a[0]), "r"(a[1]), "r"(a[2]), "r"(a[3]), "r"(b0), "r"(b1));
}

__device__ __forceinline__ void ldm_x4(uint32_t* r, uint32_t a) {
    asm volatile("ldmatrix.sync.aligned.m8n8.x4.shared.b16 {%0,%1,%2,%3}, [%4];"
        : "=r"(r[0]), "=r"(r[1]), "=r"(r[2]), "=r"(r[3]) : "r"(a));
}
__device__ __forceinline__ void ldm_x4_t(uint32_t* r, uint32_t a) {
    asm volatile("ldmatrix.sync.aligned.m8n8.x4.trans.shared.b16 {%0,%1,%2,%3}, [%4];"
        : "=r"(r[0]), "=r"(r[1]), "=r"(r[2]), "=r"(r[3]) : "r"(a));
}

__device__ __forceinline__ void cp16(uint32_t dst, const void* src) {
    asm volatile("cp.async.cg.shared.global [%0], [%1], 16;"
        :: "r"(dst), "l"(src) : "memory");
}
#define CP_COMMIT() asm volatile("cp.async.commit_group;" ::: "memory")
#define CP_WAIT(N)  asm volatile("cp.async.wait_group %0;" :: "n"(N) : "memory")

// swizzled byte offsets (computed once; k-steps advance via XOR)
__device__ __forceinline__ uint32_t swoff128(int row, int unit) {
    uint32_t off = (uint32_t)row * 128u + (uint32_t)unit * 16u;
    return off ^ ((off >> 3) & 0x70u);
}
__device__ __forceinline__ uint32_t swoff64(int row, int unit) {
    uint32_t off = (uint32_t)row * 64u + (uint32_t)unit * 16u;
    return off ^ ((off >> 3) & 0x30u);
}

// split float pair -> packed bf16x2 hi (returned) and lo (out param).
// Fast path: cvt.rn.bf16x2.f32 packs both halves in one instruction;
// hi floats reconstructed exactly (bf16 = top 16 bits of fp32).
__device__ __forceinline__ uint32_t split2(float x, float y, uint32_t& lo) {
    uint32_t hi;
    asm("cvt.rn.bf16x2.f32 %0, %1, %2;" : "=r"(hi) : "f"(y), "f"(x));
    float hx = __uint_as_float(hi << 16);
    float hy = __uint_as_float(hi & 0xFFFF0000u);
    asm("cvt.rn.bf16x2.f32 %0, %1, %2;" : "=r"(lo) : "f"(y - hy), "f"(x - hx));
    return hi;
}

// ---------------------------------------------------------------------------
// Scratch (allocation-guard-safe: __device__ globals), all bf16 hi/lo pairs
// ---------------------------------------------------------------------------
#define QKV_ELEMS ((size_t)Bv * Hv * Sv * HDv)
__device__ __nv_bfloat16 g_qhi[QKV_ELEMS], g_qlo[QKV_ELEMS];
__device__ __nv_bfloat16 g_khi[QKV_ELEMS], g_klo[QKV_ELEMS];
__device__ __nv_bfloat16 g_vhi[QKV_ELEMS], g_vlo[QKV_ELEMS];
__device__ __nv_bfloat16 g_xhi[(size_t)Mv * Dv], g_xlo[(size_t)Mv * Dv];
__device__ __nv_bfloat16 g_whi[(size_t)4 * Dv * Dv], g_wlo[(size_t)4 * Dv * Dv];
__device__ __nv_bfloat16 g_chi[(size_t)Mv * Dv], g_clo[(size_t)Mv * Dv];

// ---------------------------------------------------------------------------
// fp32 -> bf16 hi/lo splits
// ---------------------------------------------------------------------------
__global__ __launch_bounds__(256) void cvt_x_kernel(const float4* __restrict__ src)
{
    int i = blockIdx.x * blockDim.x + threadIdx.x;
    float4 v = src[i];
    uint32_t l0, l1;
    uint32_t h0 = split2(v.x, v.y, l0);
    uint32_t h1 = split2(v.z, v.w, l1);
    uint32_t* hp = (uint32_t*)(g_xhi + (size_t)i * 4);
    uint32_t* lp = (uint32_t*)(g_xlo + (size_t)i * 4);
    hp[0] = h0; hp[1] = h1;
    lp[0] = l0; lp[1] = l1;
}

__global__ __launch_bounds__(256) void cvt_w_kernel(
    const float4* __restrict__ w0, const float4* __restrict__ w1,
    const float4* __restrict__ w2, const float4* __restrict__ w3)
{
    int i = blockIdx.x * blockDim.x + threadIdx.x;
    int w = blockIdx.y;
    const float4* src = (w == 0) ? w0 : (w == 1) ? w1 : (w == 2) ? w2 : w3;
    __nv_bfloat16* hi = g_whi + (size_t)w * Dv * Dv;
    __nv_bfloat16* lo = g_wlo + (size_t)w * Dv * Dv;
    float4 v = src[i];
    uint32_t l0, l1;
    uint32_t h0 = split2(v.x, v.y, l0);
    uint32_t h1 = split2(v.z, v.w, l1);
    uint32_t* hp = (uint32_t*)(hi + (size_t)i * 4);
    uint32_t* lp = (uint32_t*)(lo + (size_t)i * 4);
    hp[0] = h0; hp[1] = h1;
    lp[0] = l0; lp[1] = l1;
}

// ---------------------------------------------------------------------------
// Tensor-core GEMM: Out[M,N] = A[M,K] @ B[N,K]^T, bf16 hi/lo 3-pass, fp32 acc.
// Block 128x128, BK=32, 8 warps (warp tile 64x32), 3-stage cp.async pipeline.
// ---------------------------------------------------------------------------
#define STG 32768
#define GEMM_SMEM (3 * STG)
#define NCH 32

__global__ __launch_bounds__(256, 2) void gemm_tc(
    int mode, float* __restrict__ out, const float* __restrict__ bias)
{
    extern __shared__ char smem[];
    uint32_t sb = smem_to_u32(smem);
    const int tid = threadIdx.x;
    const int wid = tid >> 5, lane = tid & 31;
    const int wm = wid & 1, wn = wid >> 1;
    const int m0 = blockIdx.y * 128, n0 = blockIdx.x * 128;

    const __nv_bfloat16 *Ahi, *Alo, *Bhi, *Blo;
    if (mode == 0) {
        int w = blockIdx.z;
        Ahi = g_xhi; Alo = g_xlo;
        Bhi = g_whi + (size_t)w * Dv * Dv;
        Blo = g_wlo + (size_t)w * Dv * Dv;
    } else {
        Ahi = g_chi; Alo = g_clo;
        Bhi = g_whi + (size_t)3 * Dv * Dv;
        Blo = g_wlo + (size_t)3 * Dv * Dv;
    }

    // Precomputed cp.async store offsets + gmem source offsets (per thread)
    const int r0_ = tid >> 2, u0_ = tid & 3;
    const int r1_ = (tid + 256) >> 2;
    const uint32_t st0 = swoff64(r0_, u0_), st1 = swoff64(r1_, u0_);
    const size_t ga0 = (size_t)(m0 + r0_) * Dv + u0_ * 8;
    const size_t ga1 = (size_t)(m0 + r1_) * Dv + u0_ * 8;
    const size_t gb0 = (size_t)(n0 + r0_) * Dv + u0_ * 8;
    const size_t gb1 = (size_t)(n0 + r1_) * Dv + u0_ * 8;

    auto issue = [&](int ch, int stg) {
        uint32_t base = sb + (uint32_t)stg * STG;
        int k0 = ch * 32;
        cp16(base + st0,          Ahi + ga0 + k0);
        cp16(base + 8192 + st0,   Alo + ga0 + k0);
        cp16(base + 16384 + st0,  Bhi + gb0 + k0);
        cp16(base + 24576 + st0,  Blo + gb0 + k0);
        cp16(base + st1,          Ahi + ga1 + k0);
        cp16(base + 8192 + st1,   Alo + ga1 + k0);
        cp16(base + 16384 + st1,  Bhi + gb1 + k0);
        cp16(base + 24576 + st1,  Blo + gb1 + k0);
        CP_COMMIT();
    };

    float acc[4][4][4];
#pragma unroll
    for (int i = 0; i < 4; i++)
#pragma unroll
        for (int j = 0; j < 4; j++)
#pragma unroll
            for (int k = 0; k < 4; k++) acc[i][j][k] = 0.f;

    issue(0, 0);
    issue(1, 1);

    const int lrow = lane & 15, lsel = lane >> 4;

    // Precomputed ldmatrix offsets at unit=lsel (offset bits 5-6 clear).
    // k-step advance: swizzled(off + ks*32) == swizzled(off) ^ (ks*32).
    uint32_t a_off[4], b_off[2];
#pragma unroll
    for (int mi = 0; mi < 4; mi++)
        a_off[mi] = swoff64(wm * 64 + 16 * mi + lrow, lsel);
#pragma unroll
    for (int p = 0; p < 2; p++)
        b_off[p] = swoff64(wn * 32 + 16 * p + lrow, lsel);

    for (int ch = 0; ch < NCH; ch++) {
        if (ch < NCH - 1) { CP_WAIT(1); } else { CP_WAIT(0); }
        __syncthreads();
        if (ch + 2 < NCH) issue(ch + 2, (ch + 2) % 3);

        uint32_t base = sb + (uint32_t)(ch % 3) * STG;
#pragma unroll
        for (int ks = 0; ks < 2; ks++) {
            const uint32_t kso = (uint32_t)ks * 32u;
            uint32_t ah[4][4], al[4][4], bh[2][4], bl[2][4];
#pragma unroll
            for (int mi = 0; mi < 4; mi++) {
                ldm_x4(ah[mi], base + (a_off[mi] ^ kso));
                ldm_x4(al[mi], base + 8192 + (a_off[mi] ^ kso));
            }
#pragma unroll
            for (int p = 0; p < 2; p++) {
                ldm_x4(bh[p], base + 16384 + (b_off[p] ^ kso));
                ldm_x4(bl[p], base + 24576 + (b_off[p] ^ kso));
            }
#pragma unroll
            for (int mi = 0; mi < 4; mi++)
#pragma unroll
                for (int nt = 0; nt < 4; nt++) {
                    int p = nt >> 1, q = nt & 1;
                    mma_bf16(acc[mi][nt], ah[mi], bh[p][q], bh[p][q + 2]);
                    mma_bf16(acc[mi][nt], ah[mi], bl[p][q], bl[p][q + 2]);
                    mma_bf16(acc[mi][nt], al[mi], bh[p][q], bh[p][q + 2]);
                }
        }
    }

    // Epilogue
    const int g = lane >> 2, t4 = lane & 3;
    __nv_bfloat16 *dhi = nullptr, *dlo = nullptr;
    float oscl = 1.0f;
    if (mode == 0) {
        int w = blockIdx.z;
        dhi = (w == 0) ? g_qhi : (w == 1) ? g_khi : g_vhi;
        dlo = (w == 0) ? g_qlo : (w == 1) ? g_klo : g_vlo;
        // Q pre-scale: 1/sqrt(HD) * log2(e)  (softmax uses exp2)
        if (w == 0) oscl = 0.125f * 1.44269504088896340736f;
    }
#pragma unroll
    for (int mi = 0; mi < 4; mi++)
#pragma unroll
        for (int nt = 0; nt < 4; nt++)
#pragma unroll
            for (int hf = 0; hf < 2; hf++) {
                int row = m0 + wm * 64 + 16 * mi + g + 8 * hf;
                int col = n0 + wn * 32 + 8 * nt + 2 * t4;
                float v0 = acc[mi][nt][2 * hf];
                float v1 = acc[mi][nt][2 * hf + 1];
                if (mode == 0) {
                    v0 *= oscl; v1 *= oscl;
                    int bb = row >> 11, s = row & (Sv - 1);
                    int hh = col >> 6, hd = col & 63;
                    size_t di = ((size_t)(bb * Hv + hh) * Sv + s) * HDv + hd;
                    uint32_t lo2;
                    uint32_t hi2 = split2(v0, v1, lo2);
                    *(uint32_t*)(dhi + di) = hi2;
                    *(uint32_t*)(dlo + di) = lo2;
                } else {
                    out[(size_t)row * Dv + col]     = v0 + bias[col];
                    out[(size_t)row * Dv + col + 1] = v1 + bias[col + 1];
                }
            }
}

// ---------------------------------------------------------------------------
// Tensor-core causal flash attention. BM=128, BN=64, 8 warps.
// Q pre-scaled by log2e/8; softmax in base 2 (EX2 direct).
// ---------------------------------------------------------------------------
#define ATT_SMEM (96 * 1024)

__global__ __launch_bounds__(256, 2) void attn_tc()
{
    extern __shared__ char sm_[];
    uint32_t sb = smem_to_u32(sm_);
    const int tid = threadIdx.x, wid = tid >> 5, lane = tid & 31;
    const int qt = gridDim.x - 1 - blockIdx.x;   // big tiles first
    const int h = blockIdx.y, b = blockIdx.z;
    const int q0 = qt * 128;
    const size_t hb = (size_t)(b * Hv + h) * Sv * HDv;
    const __nv_bfloat16 *Qhi = g_qhi + hb, *Qlo = g_qlo + hb;
    const __nv_bfloat16 *Khi = g_khi + hb, *Klo = g_klo + hb;
    const __nv_bfloat16 *Vhi = g_vhi + hb, *Vlo = g_vlo + hb;

    // Q tiles via cp.async (128 rows x 8 units, hi+lo)
#pragma unroll
    for (int it = 0; it < 4; it++) {
        int idx = tid + it * 256;
        int row = idx >> 3, u = idx & 7;
        uint32_t so = swoff128(row, u);
        size_t gs = (size_t)(q0 + row) * HDv + u * 8;
        cp16(sb + so,         Qhi + gs);
        cp16(sb + 16384 + so, Qlo + gs);
    }
    CP_COMMIT();

    // Precomputed KV store offsets + source offsets
    const int kr0 = tid >> 3, ku0 = tid & 7;
    const int kr1 = (tid + 256) >> 3;
    const uint32_t kst0 = swoff128(kr0, ku0), kst1 = swoff128(kr1, ku0);
    const size_t ksrc0 = (size_t)kr0 * HDv + ku0 * 8;
    const size_t ksrc1 = (size_t)kr1 * HDv + ku0 * 8;

    auto issue_kv = [&](int kt, int stg) {
        uint32_t base = sb + 32768 + (uint32_t)stg * 32768;
        size_t adv = (size_t)kt * 64 * HDv;
        cp16(base + kst0,          Khi + adv + ksrc0);
        cp16(base + 8192 + kst0,   Klo + adv + ksrc0);
        cp16(base + 16384 + kst0,  Vhi + adv + ksrc0);
        cp16(base + 24576 + kst0,  Vlo + adv + ksrc0);
        cp16(base + kst1,          Khi + adv + ksrc1);
        cp16(base + 8192 + kst1,   Klo + adv + ksrc1);
        cp16(base + 16384 + kst1,  Vhi + adv + ksrc1);
        cp16(base + 24576 + kst1,  Vlo + adv + ksrc1);
        CP_COMMIT();
    };

    issue_kv(0, 0);

    const int lrow = lane & 15, lsel = lane >> 4, g = lane >> 2, t4 = lane & 3;

    // Precomputed ldmatrix offsets; k-step via XOR, V row-advance via +2048.
    const uint32_t q_off = swoff128(wid * 16 + lrow, lsel);
    uint32_t k_off[4], v_off[4];
#pragma unroll
    for (int p = 0; p < 4; p++) k_off[p] = swoff128(16 * p + lrow, lsel);
#pragma unroll
    for (int p2 = 0; p2 < 4; p2++) v_off[p2] = swoff128(lrow, 2 * p2 + lsel);

    float mreg[2] = {-1e30f, -1e30f}, lreg[2] = {0.f, 0.f};
    float o[8][4];
#pragma unroll
    for (int nt = 0; nt < 8; nt++)
#pragma unroll
        for (int k = 0; k < 4; k++) o[nt][k] = 0.f;

    const int gq0 = q0 + wid * 16 + g;
    const int gq1 = gq0 + 8;
    const int ntiles = 2 * qt + 2;

    for (int kt = 0; kt < ntiles; kt++) {
        CP_WAIT(0);
        __syncthreads();
        if (kt + 1 < ntiles) issue_kv(kt + 1, (kt + 1) & 1);

        uint32_t kvb = sb + 32768 + (uint32_t)(kt & 1) * 32768;
        const int k0r = kt * 64;

        // ---- S = Q K^T (3-pass hi/lo); Q pre-scaled by log2e/8 ----
        float s[8][4];
#pragma unroll
        for (int nt = 0; nt < 8; nt++)
#pragma unroll
            for (int k = 0; k < 4; k++) s[nt][k] = 0.f;

#pragma unroll
        for (int ks = 0; ks < 4; ks++) {
            const uint32_t kso = (uint32_t)ks * 32u;
            uint32_t qh[4], ql[4];
            ldm_x4(qh, sb + (q_off ^ kso));
            ldm_x4(ql, sb + 16384 + (q_off ^ kso));
            uint32_t kh[4][4], kl[4][4];
#pragma unroll
            for (int p = 0; p < 4; p++) {
                ldm_x4(kh[p], kvb + (k_off[p] ^ kso));
                ldm_x4(kl[p], kvb + 8192 + (k_off[p] ^ kso));
            }
#pragma unroll
            for (int nt = 0; nt < 8; nt++) {
                int p = nt >> 1, q = nt & 1;
                mma_bf16(s[nt], qh, kh[p][q], kh[p][q + 2]);
                mma_bf16(s[nt], qh, kl[p][q], kl[p][q + 2]);
                mma_bf16(s[nt], ql, kh[p][q], kh[p][q + 2]);
            }
        }

        // causal mask (only diagonal-region tiles)
        if (kt >= 2 * qt) {
#pragma unroll
            for (int nt = 0; nt < 8; nt++) {
                int c0 = k0r + 8 * nt + 2 * t4;
                if (c0 > gq0)     s[nt][0] = -1e30f;
                if (c0 + 1 > gq0) s[nt][1] = -1e30f;
                if (c0 > gq1)     s[nt][2] = -1e30f;
                if (c0 + 1 > gq1) s[nt][3] = -1e30f;
            }
        }

        // ---- online softmax (base 2) ----
        float rm0 = -1e30f, rm1 = -1e30f;
#pragma unroll
        for (int nt = 0; nt < 8; nt++) {
            rm0 = fmaxf(rm0, fmaxf(s[nt][0], s[nt][1]));
            rm1 = fmaxf(rm1, fmaxf(s[nt][2], s[nt][3]));
        }
        rm0 = fmaxf(rm0, __shfl_xor_sync(0xffffffffu, rm0, 1));
        rm0 = fmaxf(rm0, __shfl_xor_sync(0xffffffffu, rm0, 2));
        rm1 = fmaxf(rm1, __shfl_xor_sync(0xffffffffu, rm1, 1));
        rm1 = fmaxf(rm1, __shfl_xor_sync(0xffffffffu, rm1, 2));

        float nm0 = fmaxf(mreg[0], rm0), nm1 = fmaxf(mreg[1], rm1);
        float a0 = exp2f(mreg[0] - nm0), a1 = exp2f(mreg[1] - nm1);
        mreg[0] = nm0; mreg[1] = nm1;

        float rs0 = 0.f, rs1 = 0.f;
#pragma unroll
        for (int nt = 0; nt < 8; nt++) {
            s[nt][0] = exp2f(s[nt][0] - nm0);
            s[nt][1] = exp2f(s[nt][1] - nm0);
            s[nt][2] = exp2f(s[nt][2] - nm1);
            s[nt][3] = exp2f(s[nt][3] - nm1);
            rs0 += s[nt][0] + s[nt][1];
            rs1 += s[nt][2] + s[nt][3];
        }
        rs0 += __shfl_xor_sync(0xffffffffu, rs0, 1);
        rs0 += __shfl_xor_sync(0xffffffffu, rs0, 2);
        rs1 += __shfl_xor_sync(0xffffffffu, rs1, 1);
        rs1 += __shfl_xor_sync(0xffffffffu, rs1, 2);
        lreg[0] = lreg[0] * a0 + rs0;
        lreg[1] = lreg[1] * a1 + rs1;

#pragma unroll
        for (int nt = 0; nt < 8; nt++) {
            o[nt][0] *= a0; o[nt][1] *= a0;
            o[nt][2] *= a1; o[nt][3] *= a1;
        }

        // ---- O += P V (3-pass) ----
#pragma unroll
        for (int ks = 0; ks < 4; ks++) {
            const uint32_t vko = (uint32_t)ks * 2048u;
            uint32_t ph[4], pl[4];
            ph[0] = split2(s[2 * ks][0],     s[2 * ks][1],     pl[0]);
            ph[1] = split2(s[2 * ks][2],     s[2 * ks][3],     pl[1]);
            ph[2] = split2(s[2 * ks + 1][0], s[2 * ks + 1][1], pl[2]);
            ph[3] = split2(s[2 * ks + 1][2], s[2 * ks + 1][3], pl[3]);

            uint32_t vh[4][4], vl[4][4];
#pragma unroll
            for (int p2 = 0; p2 < 4; p2++) {
                ldm_x4_t(vh[p2], kvb + 16384 + v_off[p2] + vko);
                ldm_x4_t(vl[p2], kvb + 24576 + v_off[p2] + vko);
            }
#pragma unroll
            for (int nt = 0; nt < 8; nt++) {
                int p2 = nt >> 1, q = nt & 1;
                uint32_t b0h = vh[p2][2 * q], b1h = vh[p2][2 * q + 1];
                uint32_t b0l = vl[p2][2 * q], b1l = vl[p2][2 * q + 1];
                mma_bf16(o[nt], ph, b0h, b1h);
                mma_bf16(o[nt], pl, b0h, b1h);
                mma_bf16(o[nt], ph, b0l, b1l);
            }
        }
    }

    // Epilogue: normalize, split hi/lo, write ctx [B*S, D]
    float inv0 = 1.f / lreg[0], inv1 = 1.f / lreg[1];
#pragma unroll
    for (int nt = 0; nt < 8; nt++) {
        int col = h * HDv + 8 * nt + 2 * t4;
        size_t r0 = ((size_t)b * Sv + gq0) * Dv + col;
        size_t r1 = ((size_t)b * Sv + gq1) * Dv + col;
        uint32_t lo2;
        uint32_t hi2 = split2(o[nt][0] * inv0, o[nt][1] * inv0, lo2);
        *(uint32_t*)(g_chi + r0) = hi2;
        *(uint32_t*)(g_clo + r0) = lo2;
        hi2 = split2(o[nt][2] * inv1, o[nt][3] * inv1, lo2);
        *(uint32_t*)(g_chi + r1) = hi2;
        *(uint32_t*)(g_clo + r1) = lo2;
    }
}

// ---------------------------------------------------------------------------
extern "C" void kernel_launch(void* const* d_in, const int* in_sizes, int n_in,
                              void* d_out, int out_size)
{
    const float* X  = (const float*)d_in[0];
    const float* Wq = (const float*)d_in[1];
    const float* Wk = (const float*)d_in[2];
    const float* Wv = (const float*)d_in[3];
    const float* Wo = (const float*)d_in[4];
    const float* bo = (const float*)d_in[5];
    float* out = (float*)d_out;

    cudaFuncSetAttribute(gemm_tc,
                         cudaFuncAttributeMaxDynamicSharedMemorySize, GEMM_SMEM);
    cudaFuncSetAttribute(attn_tc,
                         cudaFuncAttributeMaxDynamicSharedMemorySize, ATT_SMEM);

    const int nX4 = Mv * Dv / 4;
    const int nW4 = Dv * Dv / 4;

    cvt_x_kernel<<<nX4 / 256, 256>>>((const float4*)X);
    cvt_w_kernel<<<dim3(nW4 / 256, 4), 256>>>(
        (const float4*)Wq, (const float4*)Wk, (const float4*)Wv, (const float4*)Wo);

    gemm_tc<<<dim3(Dv / 128, Mv / 128, 3), 256, GEMM_SMEM>>>(0, nullptr, nullptr);

    attn_tc<<<dim3(Sv / 128, Hv, Bv), 256, ATT_SMEM>>>();

    gemm_tc<<<dim3(Dv / 128, Mv / 128, 1), 256, GEMM_SMEM>>>(1, out, bo);
}

// round 9
// speedup vs baseline: 1.5281x; 1.5281x over previous
#include <cuda_runtime.h>
#include <cuda_bf16.h>
#include <math.h>
#include <stdint.h>

// Problem constants
#define Bv 4
#define Sv 2048
#define Dv 1024
#define Hv 16
#define HDv 64
#define Mv (Bv * Sv)   // 8192 rows

// ---------------------------------------------------------------------------
// PTX helpers (sm_80+ baseline: mma.sync / ldmatrix / cp.async)
// ---------------------------------------------------------------------------
__device__ __forceinline__ uint32_t smem_to_u32(const void* p) {
    uint32_t a;
    asm("{ .reg .u64 t; cvta.to.shared.u64 t, %1; cvt.u32.u64 %0, t; }"
        : "=r"(a) : "l"(p));
    return a;
}

__device__ __forceinline__ void mma_bf16(float* c, const uint32_t* a,
                                         uint32_t b0, uint32_t b1) {
    asm volatile(
        "mma.sync.aligned.m16n8k16.row.col.f32.bf16.bf16.f32 "
        "{%0,%1,%2,%3}, {%4,%5,%6,%7}, {%8,%9}, {%0,%1,%2,%3};\n"
        : "+f"(c[0]), "+f"(c[1]), "+f"(c[2]), "+f"(c[3])
        : "r"(a[0]), "r"(a[1]), "r"(a[2]), "r"(a[3]), "r"(b0), "r"(b1));
}

__device__ __forceinline__ void ldm_x4(uint32_t* r, uint32_t a) {
    asm volatile("ldmatrix.sync.aligned.m8n8.x4.shared.b16 {%0,%1,%2,%3}, [%4];"
        : "=r"(r[0]), "=r"(r[1]), "=r"(r[2]), "=r"(r[3]) : "r"(a));
}
__device__ __forceinline__ void ldm_x4_t(uint32_t* r, uint32_t a) {
    asm volatile("ldmatrix.sync.aligned.m8n8.x4.trans.shared.b16 {%0,%1,%2,%3}, [%4];"
        : "=r"(r[0]), "=r"(r[1]), "=r"(r[2]), "=r"(r[3]) : "r"(a));
}

__device__ __forceinline__ void cp16(uint32_t dst, const void* src) {
    asm volatile("cp.async.cg.shared.global [%0], [%1], 16;"
        :: "r"(dst), "l"(src) : "memory");
}
#define CP_COMMIT() asm volatile("cp.async.commit_group;" ::: "memory")
#define CP_WAIT(N)  asm volatile("cp.async.wait_group %0;" :: "n"(N) : "memory")

// hardware EX2 (what __expf lowers to, without the extra log2e FMUL)
__device__ __forceinline__ float ex2(float x) {
    float y;
    asm("ex2.approx.ftz.f32 %0, %1;" : "=f"(y) : "f"(x));
    return y;
}

// swizzled byte offsets (computed once; k-steps advance via XOR)
__device__ __forceinline__ uint32_t swoff128(int row, int unit) {
    uint32_t off = (uint32_t)row * 128u + (uint32_t)unit * 16u;
    return off ^ ((off >> 3) & 0x70u);
}
__device__ __forceinline__ uint32_t swoff64(int row, int unit) {
    uint32_t off = (uint32_t)row * 64u + (uint32_t)unit * 16u;
    return off ^ ((off >> 3) & 0x30u);
}

// split float pair -> packed bf16x2 hi (returned) and lo (out param)
__device__ __forceinline__ uint32_t split2(float x, float y, uint32_t& lo) {
    __nv_bfloat16 hx = __float2bfloat16(x);
    __nv_bfloat16 hy = __float2bfloat16(y);
    __nv_bfloat162 hp(hx, hy);
    __nv_bfloat162 lp(__float2bfloat16(x - __bfloat162float(hx)),
                      __float2bfloat16(y - __bfloat162float(hy)));
    lo = *(uint32_t*)&lp;
    return *(uint32_t*)&hp;
}

// ---------------------------------------------------------------------------
// Scratch (allocation-guard-safe: __device__ globals), all bf16 hi/lo pairs
// ---------------------------------------------------------------------------
#define QKV_ELEMS ((size_t)Bv * Hv * Sv * HDv)
__device__ __nv_bfloat16 g_qhi[QKV_ELEMS], g_qlo[QKV_ELEMS];
__device__ __nv_bfloat16 g_khi[QKV_ELEMS], g_klo[QKV_ELEMS];
__device__ __nv_bfloat16 g_vhi[QKV_ELEMS], g_vlo[QKV_ELEMS];
__device__ __nv_bfloat16 g_xhi[(size_t)Mv * Dv], g_xlo[(size_t)Mv * Dv];
__device__ __nv_bfloat16 g_whi[(size_t)4 * Dv * Dv], g_wlo[(size_t)4 * Dv * Dv];
__device__ __nv_bfloat16 g_chi[(size_t)Mv * Dv], g_clo[(size_t)Mv * Dv];

// ---------------------------------------------------------------------------
// fp32 -> bf16 hi/lo splits
// ---------------------------------------------------------------------------
__global__ __launch_bounds__(256) void cvt_x_kernel(const float4* __restrict__ src)
{
    int i = blockIdx.x * blockDim.x + threadIdx.x;
    float4 v = src[i];
    uint32_t l0, l1;
    uint32_t h0 = split2(v.x, v.y, l0);
    uint32_t h1 = split2(v.z, v.w, l1);
    uint32_t* hp = (uint32_t*)(g_xhi + (size_t)i * 4);
    uint32_t* lp = (uint32_t*)(g_xlo + (size_t)i * 4);
    hp[0] = h0; hp[1] = h1;
    lp[0] = l0; lp[1] = l1;
}

__global__ __launch_bounds__(256) void cvt_w_kernel(
    const float4* __restrict__ w0, const float4* __restrict__ w1,
    const float4* __restrict__ w2, const float4* __restrict__ w3)
{
    int i = blockIdx.x * blockDim.x + threadIdx.x;
    int w = blockIdx.y;
    const float4* src = (w == 0) ? w0 : (w == 1) ? w1 : (w == 2) ? w2 : w3;
    __nv_bfloat16* hi = g_whi + (size_t)w * Dv * Dv;
    __nv_bfloat16* lo = g_wlo + (size_t)w * Dv * Dv;
    float4 v = src[i];
    uint32_t l0, l1;
    uint32_t h0 = split2(v.x, v.y, l0);
    uint32_t h1 = split2(v.z, v.w, l1);
    uint32_t* hp = (uint32_t*)(hi + (size_t)i * 4);
    uint32_t* lp = (uint32_t*)(lo + (size_t)i * 4);
    hp[0] = h0; hp[1] = h1;
    lp[0] = l0; lp[1] = l1;
}

// ---------------------------------------------------------------------------
// Tensor-core GEMM: Out[M,N] = A[M,K] @ B[N,K]^T, bf16 hi/lo 3-pass, fp32 acc.
// Block 128x128, BK=32, 8 warps (warp tile 64x32), 3-stage cp.async pipeline.
// ---------------------------------------------------------------------------
#define STG 32768
#define GEMM_SMEM (3 * STG)
#define NCH 32

__global__ __launch_bounds__(256, 2) void gemm_tc(
    int mode, float* __restrict__ out, const float* __restrict__ bias)
{
    extern __shared__ char smem[];
    uint32_t sb = smem_to_u32(smem);
    const int tid = threadIdx.x;
    const int wid = tid >> 5, lane = tid & 31;
    const int wm = wid & 1, wn = wid >> 1;
    const int m0 = blockIdx.y * 128, n0 = blockIdx.x * 128;

    const __nv_bfloat16 *Ahi, *Alo, *Bhi, *Blo;
    if (mode == 0) {
        int w = blockIdx.z;
        Ahi = g_xhi; Alo = g_xlo;
        Bhi = g_whi + (size_t)w * Dv * Dv;
        Blo = g_wlo + (size_t)w * Dv * Dv;
    } else {
        Ahi = g_chi; Alo = g_clo;
        Bhi = g_whi + (size_t)3 * Dv * Dv;
        Blo = g_wlo + (size_t)3 * Dv * Dv;
    }

    // Precomputed cp.async store offsets + gmem source offsets (per thread)
    const int r0_ = tid >> 2, u0_ = tid & 3;
    const int r1_ = (tid + 256) >> 2;
    const uint32_t st0 = swoff64(r0_, u0_), st1 = swoff64(r1_, u0_);
    const size_t ga0 = (size_t)(m0 + r0_) * Dv + u0_ * 8;
    const size_t ga1 = (size_t)(m0 + r1_) * Dv + u0_ * 8;
    const size_t gb0 = (size_t)(n0 + r0_) * Dv + u0_ * 8;
    const size_t gb1 = (size_t)(n0 + r1_) * Dv + u0_ * 8;

    auto issue = [&](int ch, int stg) {
        uint32_t base = sb + (uint32_t)stg * STG;
        int k0 = ch * 32;
        cp16(base + st0,          Ahi + ga0 + k0);
        cp16(base + 8192 + st0,   Alo + ga0 + k0);
        cp16(base + 16384 + st0,  Bhi + gb0 + k0);
        cp16(base + 24576 + st0,  Blo + gb0 + k0);
        cp16(base + st1,          Ahi + ga1 + k0);
        cp16(base + 8192 + st1,   Alo + ga1 + k0);
        cp16(base + 16384 + st1,  Bhi + gb1 + k0);
        cp16(base + 24576 + st1,  Blo + gb1 + k0);
        CP_COMMIT();
    };

    float acc[4][4][4];
#pragma unroll
    for (int i = 0; i < 4; i++)
#pragma unroll
        for (int j = 0; j < 4; j++)
#pragma unroll
            for (int k = 0; k < 4; k++) acc[i][j][k] = 0.f;

    issue(0, 0);
    issue(1, 1);

    const int lrow = lane & 15, lsel = lane >> 4;

    // Precomputed ldmatrix offsets at unit=lsel (offset bits 5-6 clear).
    // k-step advance: swizzled(off + ks*32) == swizzled(off) ^ (ks*32).
    uint32_t a_off[4], b_off[2];
#pragma unroll
    for (int mi = 0; mi < 4; mi++)
        a_off[mi] = swoff64(wm * 64 + 16 * mi + lrow, lsel);
#pragma unroll
    for (int p = 0; p < 2; p++)
        b_off[p] = swoff64(wn * 32 + 16 * p + lrow, lsel);

    for (int ch = 0; ch < NCH; ch++) {
        if (ch < NCH - 1) { CP_WAIT(1); } else { CP_WAIT(0); }
        __syncthreads();
        if (ch + 2 < NCH) issue(ch + 2, (ch + 2) % 3);

        uint32_t base = sb + (uint32_t)(ch % 3) * STG;
#pragma unroll
        for (int ks = 0; ks < 2; ks++) {
            const uint32_t kso = (uint32_t)ks * 32u;
            uint32_t ah[4][4], al[4][4], bh[2][4], bl[2][4];
#pragma unroll
            for (int mi = 0; mi < 4; mi++) {
                ldm_x4(ah[mi], base + (a_off[mi] ^ kso));
                ldm_x4(al[mi], base + 8192 + (a_off[mi] ^ kso));
            }
#pragma unroll
            for (int p = 0; p < 2; p++) {
                ldm_x4(bh[p], base + 16384 + (b_off[p] ^ kso));
                ldm_x4(bl[p], base + 24576 + (b_off[p] ^ kso));
            }
#pragma unroll
            for (int mi = 0; mi < 4; mi++)
#pragma unroll
                for (int nt = 0; nt < 4; nt++) {
                    int p = nt >> 1, q = nt & 1;
                    mma_bf16(acc[mi][nt], ah[mi], bh[p][q], bh[p][q + 2]);
                    mma_bf16(acc[mi][nt], ah[mi], bl[p][q], bl[p][q + 2]);
                    mma_bf16(acc[mi][nt], al[mi], bh[p][q], bh[p][q + 2]);
                }
        }
    }

    // Epilogue
    const int g = lane >> 2, t4 = lane & 3;
    __nv_bfloat16 *dhi = nullptr, *dlo = nullptr;
    float oscl = 1.0f;
    if (mode == 0) {
        int w = blockIdx.z;
        dhi = (w == 0) ? g_qhi : (w == 1) ? g_khi : g_vhi;
        dlo = (w == 0) ? g_qlo : (w == 1) ? g_klo : g_vlo;
        // Q pre-scale: 1/sqrt(HD) * log2(e)  (softmax uses EX2 directly)
        if (w == 0) oscl = 0.125f * 1.44269504088896340736f;
    }
#pragma unroll
    for (int mi = 0; mi < 4; mi++)
#pragma unroll
        for (int nt = 0; nt < 4; nt++)
#pragma unroll
            for (int hf = 0; hf < 2; hf++) {
                int row = m0 + wm * 64 + 16 * mi + g + 8 * hf;
                int col = n0 + wn * 32 + 8 * nt + 2 * t4;
                float v0 = acc[mi][nt][2 * hf];
                float v1 = acc[mi][nt][2 * hf + 1];
                if (mode == 0) {
                    v0 *= oscl; v1 *= oscl;
                    int bb = row >> 11, s = row & (Sv - 1);
                    int hh = col >> 6, hd = col & 63;
                    size_t di = ((size_t)(bb * Hv + hh) * Sv + s) * HDv + hd;
                    uint32_t lo2;
                    uint32_t hi2 = split2(v0, v1, lo2);
                    *(uint32_t*)(dhi + di) = hi2;
                    *(uint32_t*)(dlo + di) = lo2;
                } else {
                    out[(size_t)row * Dv + col]     = v0 + bias[col];
                    out[(size_t)row * Dv + col + 1] = v1 + bias[col + 1];
                }
            }
}

// ---------------------------------------------------------------------------
// Tensor-core causal flash attention. BM=128, BN=64, 8 warps.
// Q pre-scaled by log2e/8; softmax via EX2 (base 2).
// ---------------------------------------------------------------------------
#define ATT_SMEM (96 * 1024)

__global__ __launch_bounds__(256, 2) void attn_tc()
{
    extern __shared__ char sm_[];
    uint32_t sb = smem_to_u32(sm_);
    const int tid = threadIdx.x, wid = tid >> 5, lane = tid & 31;
    const int qt = gridDim.x - 1 - blockIdx.x;   // big tiles first
    const int h = blockIdx.y, b = blockIdx.z;
    const int q0 = qt * 128;
    const size_t hb = (size_t)(b * Hv + h) * Sv * HDv;
    const __nv_bfloat16 *Qhi = g_qhi + hb, *Qlo = g_qlo + hb;
    const __nv_bfloat16 *Khi = g_khi + hb, *Klo = g_klo + hb;
    const __nv_bfloat16 *Vhi = g_vhi + hb, *Vlo = g_vlo + hb;

    // Q tiles via cp.async (128 rows x 8 units, hi+lo)
#pragma unroll
    for (int it = 0; it < 4; it++) {
        int idx = tid + it * 256;
        int row = idx >> 3, u = idx & 7;
        uint32_t so = swoff128(row, u);
        size_t gs = (size_t)(q0 + row) * HDv + u * 8;
        cp16(sb + so,         Qhi + gs);
        cp16(sb + 16384 + so, Qlo + gs);
    }
    CP_COMMIT();

    // Precomputed KV store offsets + source offsets
    const int kr0 = tid >> 3, ku0 = tid & 7;
    const int kr1 = (tid + 256) >> 3;
    const uint32_t kst0 = swoff128(kr0, ku0), kst1 = swoff128(kr1, ku0);
    const size_t ksrc0 = (size_t)kr0 * HDv + ku0 * 8;
    const size_t ksrc1 = (size_t)kr1 * HDv + ku0 * 8;

    auto issue_kv = [&](int kt, int stg) {
        uint32_t base = sb + 32768 + (uint32_t)stg * 32768;
        size_t adv = (size_t)kt * 64 * HDv;
        cp16(base + kst0,          Khi + adv + ksrc0);
        cp16(base + 8192 + kst0,   Klo + adv + ksrc0);
        cp16(base + 16384 + kst0,  Vhi + adv + ksrc0);
        cp16(base + 24576 + kst0,  Vlo + adv + ksrc0);
        cp16(base + kst1,          Khi + adv + ksrc1);
        cp16(base + 8192 + kst1,   Klo + adv + ksrc1);
        cp16(base + 16384 + kst1,  Vhi + adv + ksrc1);
        cp16(base + 24576 + kst1,  Vlo + adv + ksrc1);
        CP_COMMIT();
    };

    issue_kv(0, 0);

    const int lrow = lane & 15, lsel = lane >> 4, g = lane >> 2, t4 = lane & 3;

    // Precomputed ldmatrix offsets; k-step via XOR, V row-advance via +2048.
    const uint32_t q_off = swoff128(wid * 16 + lrow, lsel);
    uint32_t k_off[4], v_off[4];
#pragma unroll
    for (int p = 0; p < 4; p++) k_off[p] = swoff128(16 * p + lrow, lsel);
#pragma unroll
    for (int p2 = 0; p2 < 4; p2++) v_off[p2] = swoff128(lrow, 2 * p2 + lsel);

    float mreg[2] = {-1e30f, -1e30f}, lreg[2] = {0.f, 0.f};
    float o[8][4];
#pragma unroll
    for (int nt = 0; nt < 8; nt++)
#pragma unroll
        for (int k = 0; k < 4; k++) o[nt][k] = 0.f;

    const int gq0 = q0 + wid * 16 + g;
    const int gq1 = gq0 + 8;
    const int ntiles = 2 * qt + 2;

    for (int kt = 0; kt < ntiles; kt++) {
        CP_WAIT(0);
        __syncthreads();
        if (kt + 1 < ntiles) issue_kv(kt + 1, (kt + 1) & 1);

        uint32_t kvb = sb + 32768 + (uint32_t)(kt & 1) * 32768;
        const int k0r = kt * 64;

        // ---- S = Q K^T (3-pass hi/lo); scores already base-2 scaled ----
        float s[8][4];
#pragma unroll
        for (int nt = 0; nt < 8; nt++)
#pragma unroll
            for (int k = 0; k < 4; k++) s[nt][k] = 0.f;

#pragma unroll
        for (int ks = 0; ks < 4; ks++) {
            const uint32_t kso = (uint32_t)ks * 32u;
            uint32_t qh[4], ql[4];
            ldm_x4(qh, sb + (q_off ^ kso));
            ldm_x4(ql, sb + 16384 + (q_off ^ kso));
            uint32_t kh[4][4], kl[4][4];
#pragma unroll
            for (int p = 0; p < 4; p++) {
                ldm_x4(kh[p], kvb + (k_off[p] ^ kso));
                ldm_x4(kl[p], kvb + 8192 + (k_off[p] ^ kso));
            }
#pragma unroll
            for (int nt = 0; nt < 8; nt++) {
                int p = nt >> 1, q = nt & 1;
                mma_bf16(s[nt], qh, kh[p][q], kh[p][q + 2]);
                mma_bf16(s[nt], qh, kl[p][q], kl[p][q + 2]);
                mma_bf16(s[nt], ql, kh[p][q], kh[p][q + 2]);
            }
        }

        // causal mask (only diagonal-region tiles)
        if (kt >= 2 * qt) {
#pragma unroll
            for (int nt = 0; nt < 8; nt++) {
                int c0 = k0r + 8 * nt + 2 * t4;
                if (c0 > gq0)     s[nt][0] = -1e30f;
                if (c0 + 1 > gq0) s[nt][1] = -1e30f;
                if (c0 > gq1)     s[nt][2] = -1e30f;
                if (c0 + 1 > gq1) s[nt][3] = -1e30f;
            }
        }

        // ---- online softmax (base 2, hardware EX2) ----
        float rm0 = -1e30f, rm1 = -1e30f;
#pragma unroll
        for (int nt = 0; nt < 8; nt++) {
            rm0 = fmaxf(rm0, fmaxf(s[nt][0], s[nt][1]));
            rm1 = fmaxf(rm1, fmaxf(s[nt][2], s[nt][3]));
        }
        rm0 = fmaxf(rm0, __shfl_xor_sync(0xffffffffu, rm0, 1));
        rm0 = fmaxf(rm0, __shfl_xor_sync(0xffffffffu, rm0, 2));
        rm1 = fmaxf(rm1, __shfl_xor_sync(0xffffffffu, rm1, 1));
        rm1 = fmaxf(rm1, __shfl_xor_sync(0xffffffffu, rm1, 2));

        float nm0 = fmaxf(mreg[0], rm0), nm1 = fmaxf(mreg[1], rm1);
        float a0 = ex2(mreg[0] - nm0), a1 = ex2(mreg[1] - nm1);
        mreg[0] = nm0; mreg[1] = nm1;

        float rs0 = 0.f, rs1 = 0.f;
#pragma unroll
        for (int nt = 0; nt < 8; nt++) {
            s[nt][0] = ex2(s[nt][0] - nm0);
            s[nt][1] = ex2(s[nt][1] - nm0);
            s[nt][2] = ex2(s[nt][2] - nm1);
            s[nt][3] = ex2(s[nt][3] - nm1);
            rs0 += s[nt][0] + s[nt][1];
            rs1 += s[nt][2] + s[nt][3];
        }
        rs0 += __shfl_xor_sync(0xffffffffu, rs0, 1);
        rs0 += __shfl_xor_sync(0xffffffffu, rs0, 2);
        rs1 += __shfl_xor_sync(0xffffffffu, rs1, 1);
        rs1 += __shfl_xor_sync(0xffffffffu, rs1, 2);
        lreg[0] = lreg[0] * a0 + rs0;
        lreg[1] = lreg[1] * a1 + rs1;

#pragma unroll
        for (int nt = 0; nt < 8; nt++) {
            o[nt][0] *= a0; o[nt][1] *= a0;
            o[nt][2] *= a1; o[nt][3] *= a1;
        }

        // ---- O += P V (3-pass) ----
#pragma unroll
        for (int ks = 0; ks < 4; ks++) {
            const uint32_t vko = (uint32_t)ks * 2048u;
            uint32_t ph[4], pl[4];
            ph[0] = split2(s[2 * ks][0],     s[2 * ks][1],     pl[0]);
            ph[1] = split2(s[2 * ks][2],     s[2 * ks][3],     pl[1]);
            ph[2] = split2(s[2 * ks + 1][0], s[2 * ks + 1][1], pl[2]);
            ph[3] = split2(s[2 * ks + 1][2], s[2 * ks + 1][3], pl[3]);

            uint32_t vh[4][4], vl[4][4];
#pragma unroll
            for (int p2 = 0; p2 < 4; p2++) {
                ldm_x4_t(vh[p2], kvb + 16384 + v_off[p2] + vko);
                ldm_x4_t(vl[p2], kvb + 24576 + v_off[p2] + vko);
            }
#pragma unroll
            for (int nt = 0; nt < 8; nt++) {
                int p2 = nt >> 1, q = nt & 1;
                uint32_t b0h = vh[p2][2 * q], b1h = vh[p2][2 * q + 1];
                uint32_t b0l = vl[p2][2 * q], b1l = vl[p2][2 * q + 1];
                mma_bf16(o[nt], ph, b0h, b1h);
                mma_bf16(o[nt], pl, b0h, b1h);
                mma_bf16(o[nt], ph, b0l, b1l);
            }
        }
    }

    // Epilogue: normalize, split hi/lo, write ctx [B*S, D]
    float inv0 = 1.f / lreg[0], inv1 = 1.f / lreg[1];
#pragma unroll
    for (int nt = 0; nt < 8; nt++) {
        int col = h * HDv + 8 * nt + 2 * t4;
        size_t r0 = ((size_t)b * Sv + gq0) * Dv + col;
        size_t r1 = ((size_t)b * Sv + gq1) * Dv + col;
        uint32_t lo2;
        uint32_t hi2 = split2(o[nt][0] * inv0, o[nt][1] * inv0, lo2);
        *(uint32_t*)(g_chi + r0) = hi2;
        *(uint32_t*)(g_clo + r0) = lo2;
        hi2 = split2(o[nt][2] * inv1, o[nt][3] * inv1, lo2);
        *(uint32_t*)(g_chi + r1) = hi2;
        *(uint32_t*)(g_clo + r1) = lo2;
    }
}

// ---------------------------------------------------------------------------
extern "C" void kernel_launch(void* const* d_in, const int* in_sizes, int n_in,
                              void* d_out, int out_size)
{
    const float* X  = (const float*)d_in[0];
    const float* Wq = (const float*)d_in[1];
    const float* Wk = (const float*)d_in[2];
    const float* Wv = (const float*)d_in[3];
    const float* Wo = (const float*)d_in[4];
    const float* bo = (const float*)d_in[5];
    float* out = (float*)d_out;

    cudaFuncSetAttribute(gemm_tc,
                         cudaFuncAttributeMaxDynamicSharedMemorySize, GEMM_SMEM);
    cudaFuncSetAttribute(attn_tc,
                         cudaFuncAttributeMaxDynamicSharedMemorySize, ATT_SMEM);

    const int nX4 = Mv * Dv / 4;
    const int nW4 = Dv * Dv / 4;

    cvt_x_kernel<<<nX4 / 256, 256>>>((const float4*)X);
    cvt_w_kernel<<<dim3(nW4 / 256, 4), 256>>>(
        (const float4*)Wq, (const float4*)Wk, (const float4*)Wv, (const float4*)Wo);

    gemm_tc<<<dim3(Dv / 128, Mv / 128, 3), 256, GEMM_SMEM>>>(0, nullptr, nullptr);

    attn_tc<<<dim3(Sv / 128, Hv, Bv), 256, ATT_SMEM>>>();

    gemm_tc<<<dim3(Dv / 128, Mv / 128, 1), 256, GEMM_SMEM>>>(1, out, bo);
}

// round 10
// speedup vs baseline: 1.5481x; 1.0131x over previous
#include <cuda_runtime.h>
#include <cuda_bf16.h>
#include <math.h>
#include <stdint.h>

// Problem constants
#define Bv 4
#define Sv 2048
#define Dv 1024
#define Hv 16
#define HDv 64
#define Mv (Bv * Sv)   // 8192 rows

// ---------------------------------------------------------------------------
// PTX helpers (sm_80+ baseline: mma.sync / ldmatrix / cp.async)
// ---------------------------------------------------------------------------
__device__ __forceinline__ uint32_t smem_to_u32(const void* p) {
    uint32_t a;
    asm("{ .reg .u64 t; cvta.to.shared.u64 t, %1; cvt.u32.u64 %0, t; }"
        : "=r"(a) : "l"(p));
    return a;
}

__device__ __forceinline__ void mma_bf16(float* c, const uint32_t* a,
                                         uint32_t b0, uint32_t b1) {
    asm volatile(
        "mma.sync.aligned.m16n8k16.row.col.f32.bf16.bf16.f32 "
        "{%0,%1,%2,%3}, {%4,%5,%6,%7}, {%8,%9}, {%0,%1,%2,%3};\n"
        : "+f"(c[0]), "+f"(c[1]), "+f"(c[2]), "+f"(c[3])
        : "r"(a[0]), "r"(a[1]), "r"(a[2]), "r"(a[3]), "r"(b0), "r"(b1));
}

__device__ __forceinline__ void ldm_x4(uint32_t* r, uint32_t a) {
    asm volatile("ldmatrix.sync.aligned.m8n8.x4.shared.b16 {%0,%1,%2,%3}, [%4];"
        : "=r"(r[0]), "=r"(r[1]), "=r"(r[2]), "=r"(r[3]) : "r"(a));
}
__device__ __forceinline__ void ldm_x4_t(uint32_t* r, uint32_t a) {
    asm volatile("ldmatrix.sync.aligned.m8n8.x4.trans.shared.b16 {%0,%1,%2,%3}, [%4];"
        : "=r"(r[0]), "=r"(r[1]), "=r"(r[2]), "=r"(r[3]) : "r"(a));
}

__device__ __forceinline__ void cp16(uint32_t dst, const void* src) {
    asm volatile("cp.async.cg.shared.global [%0], [%1], 16;"
        :: "r"(dst), "l"(src) : "memory");
}
#define CP_COMMIT() asm volatile("cp.async.commit_group;" ::: "memory")
#define CP_WAIT(N)  asm volatile("cp.async.wait_group %0;" :: "n"(N) : "memory")

// hardware EX2 (what __expf lowers to, without the extra log2e FMUL)
__device__ __forceinline__ float ex2(float x) {
    float y;
    asm("ex2.approx.ftz.f32 %0, %1;" : "=f"(y) : "f"(x));
    return y;
}

// swizzled byte offsets (computed once; k-steps advance via XOR)
__device__ __forceinline__ uint32_t swoff128(int row, int unit) {
    uint32_t off = (uint32_t)row * 128u + (uint32_t)unit * 16u;
    return off ^ ((off >> 3) & 0x70u);
}
__device__ __forceinline__ uint32_t swoff64(int row, int unit) {
    uint32_t off = (uint32_t)row * 64u + (uint32_t)unit * 16u;
    return off ^ ((off >> 3) & 0x30u);
}

// split float pair -> packed bf16x2 hi (returned) and lo (out param)
__device__ __forceinline__ uint32_t split2(float x, float y, uint32_t& lo) {
    __nv_bfloat16 hx = __float2bfloat16(x);
    __nv_bfloat16 hy = __float2bfloat16(y);
    __nv_bfloat162 hp(hx, hy);
    __nv_bfloat162 lp(__float2bfloat16(x - __bfloat162float(hx)),
                      __float2bfloat16(y - __bfloat162float(hy)));
    lo = *(uint32_t*)&lp;
    return *(uint32_t*)&hp;
}

// ---------------------------------------------------------------------------
// Scratch (allocation-guard-safe: __device__ globals), all bf16 hi/lo pairs
// ---------------------------------------------------------------------------
#define QKV_ELEMS ((size_t)Bv * Hv * Sv * HDv)
__device__ __nv_bfloat16 g_qhi[QKV_ELEMS], g_qlo[QKV_ELEMS];
__device__ __nv_bfloat16 g_khi[QKV_ELEMS], g_klo[QKV_ELEMS];
__device__ __nv_bfloat16 g_vhi[QKV_ELEMS], g_vlo[QKV_ELEMS];
__device__ __nv_bfloat16 g_xhi[(size_t)Mv * Dv], g_xlo[(size_t)Mv * Dv];
__device__ __nv_bfloat16 g_whi[(size_t)4 * Dv * Dv], g_wlo[(size_t)4 * Dv * Dv];
__device__ __nv_bfloat16 g_chi[(size_t)Mv * Dv], g_clo[(size_t)Mv * Dv];

// ---------------------------------------------------------------------------
// fp32 -> bf16 hi/lo splits
// ---------------------------------------------------------------------------
__global__ __launch_bounds__(256) void cvt_x_kernel(const float4* __restrict__ src)
{
    int i = blockIdx.x * blockDim.x + threadIdx.x;
    float4 v = src[i];
    uint32_t l0, l1;
    uint32_t h0 = split2(v.x, v.y, l0);
    uint32_t h1 = split2(v.z, v.w, l1);
    uint32_t* hp = (uint32_t*)(g_xhi + (size_t)i * 4);
    uint32_t* lp = (uint32_t*)(g_xlo + (size_t)i * 4);
    hp[0] = h0; hp[1] = h1;
    lp[0] = l0; lp[1] = l1;
}

__global__ __launch_bounds__(256) void cvt_w_kernel(
    const float4* __restrict__ w0, const float4* __restrict__ w1,
    const float4* __restrict__ w2, const float4* __restrict__ w3)
{
    int i = blockIdx.x * blockDim.x + threadIdx.x;
    int w = blockIdx.y;
    const float4* src = (w == 0) ? w0 : (w == 1) ? w1 : (w == 2) ? w2 : w3;
    __nv_bfloat16* hi = g_whi + (size_t)w * Dv * Dv;
    __nv_bfloat16* lo = g_wlo + (size_t)w * Dv * Dv;
    float4 v = src[i];
    uint32_t l0, l1;
    uint32_t h0 = split2(v.x, v.y, l0);
    uint32_t h1 = split2(v.z, v.w, l1);
    uint32_t* hp = (uint32_t*)(hi + (size_t)i * 4);
    uint32_t* lp = (uint32_t*)(lo + (size_t)i * 4);
    hp[0] = h0; hp[1] = h1;
    lp[0] = l0; lp[1] = l1;
}

// ---------------------------------------------------------------------------
// Tensor-core GEMM: Out[M,N] = A[M,K] @ B[N,K]^T, bf16 hi/lo 3-pass, fp32 acc.
// Block 128x128, BK=32, 8 warps (warp tile 64x32), 3-stage cp.async pipeline.
// Pass loop OUTSIDE so consecutive MMAs hit different accumulators.
// ---------------------------------------------------------------------------
#define STG 32768
#define GEMM_SMEM (3 * STG)
#define NCH 32

__global__ __launch_bounds__(256, 2) void gemm_tc(
    int mode, float* __restrict__ out, const float* __restrict__ bias)
{
    extern __shared__ char smem[];
    uint32_t sb = smem_to_u32(smem);
    const int tid = threadIdx.x;
    const int wid = tid >> 5, lane = tid & 31;
    const int wm = wid & 1, wn = wid >> 1;
    const int m0 = blockIdx.y * 128, n0 = blockIdx.x * 128;

    const __nv_bfloat16 *Ahi, *Alo, *Bhi, *Blo;
    if (mode == 0) {
        int w = blockIdx.z;
        Ahi = g_xhi; Alo = g_xlo;
        Bhi = g_whi + (size_t)w * Dv * Dv;
        Blo = g_wlo + (size_t)w * Dv * Dv;
    } else {
        Ahi = g_chi; Alo = g_clo;
        Bhi = g_whi + (size_t)3 * Dv * Dv;
        Blo = g_wlo + (size_t)3 * Dv * Dv;
    }

    // Precomputed cp.async store offsets + gmem source offsets (per thread)
    const int r0_ = tid >> 2, u0_ = tid & 3;
    const int r1_ = (tid + 256) >> 2;
    const uint32_t st0 = swoff64(r0_, u0_), st1 = swoff64(r1_, u0_);
    const size_t ga0 = (size_t)(m0 + r0_) * Dv + u0_ * 8;
    const size_t ga1 = (size_t)(m0 + r1_) * Dv + u0_ * 8;
    const size_t gb0 = (size_t)(n0 + r0_) * Dv + u0_ * 8;
    const size_t gb1 = (size_t)(n0 + r1_) * Dv + u0_ * 8;

    auto issue = [&](int ch, int stg) {
        uint32_t base = sb + (uint32_t)stg * STG;
        int k0 = ch * 32;
        cp16(base + st0,          Ahi + ga0 + k0);
        cp16(base + 8192 + st0,   Alo + ga0 + k0);
        cp16(base + 16384 + st0,  Bhi + gb0 + k0);
        cp16(base + 24576 + st0,  Blo + gb0 + k0);
        cp16(base + st1,          Ahi + ga1 + k0);
        cp16(base + 8192 + st1,   Alo + ga1 + k0);
        cp16(base + 16384 + st1,  Bhi + gb1 + k0);
        cp16(base + 24576 + st1,  Blo + gb1 + k0);
        CP_COMMIT();
    };

    float acc[4][4][4];
#pragma unroll
    for (int i = 0; i < 4; i++)
#pragma unroll
        for (int j = 0; j < 4; j++)
#pragma unroll
            for (int k = 0; k < 4; k++) acc[i][j][k] = 0.f;

    issue(0, 0);
    issue(1, 1);

    const int lrow = lane & 15, lsel = lane >> 4;

    // Precomputed ldmatrix offsets at unit=lsel (offset bits 5-6 clear).
    // k-step advance: swizzled(off + ks*32) == swizzled(off) ^ (ks*32).
    uint32_t a_off[4], b_off[2];
#pragma unroll
    for (int mi = 0; mi < 4; mi++)
        a_off[mi] = swoff64(wm * 64 + 16 * mi + lrow, lsel);
#pragma unroll
    for (int p = 0; p < 2; p++)
        b_off[p] = swoff64(wn * 32 + 16 * p + lrow, lsel);

    for (int ch = 0; ch < NCH; ch++) {
        if (ch < NCH - 1) { CP_WAIT(1); } else { CP_WAIT(0); }
        __syncthreads();
        if (ch + 2 < NCH) issue(ch + 2, (ch + 2) % 3);

        uint32_t base = sb + (uint32_t)(ch % 3) * STG;
#pragma unroll
        for (int ks = 0; ks < 2; ks++) {
            const uint32_t kso = (uint32_t)ks * 32u;
            uint32_t ah[4][4], al[4][4], bh[2][4], bl[2][4];
#pragma unroll
            for (int mi = 0; mi < 4; mi++) {
                ldm_x4(ah[mi], base + (a_off[mi] ^ kso));
                ldm_x4(al[mi], base + 8192 + (a_off[mi] ^ kso));
            }
#pragma unroll
            for (int p = 0; p < 2; p++) {
                ldm_x4(bh[p], base + 16384 + (b_off[p] ^ kso));
                ldm_x4(bl[p], base + 24576 + (b_off[p] ^ kso));
            }
            // pass 1: hi*hi  (16 independent accumulators back-to-back)
#pragma unroll
            for (int mi = 0; mi < 4; mi++)
#pragma unroll
                for (int nt = 0; nt < 4; nt++) {
                    int p = nt >> 1, q = nt & 1;
                    mma_bf16(acc[mi][nt], ah[mi], bh[p][q], bh[p][q + 2]);
                }
            // pass 2: hi*lo
#pragma unroll
            for (int mi = 0; mi < 4; mi++)
#pragma unroll
                for (int nt = 0; nt < 4; nt++) {
                    int p = nt >> 1, q = nt & 1;
                    mma_bf16(acc[mi][nt], ah[mi], bl[p][q], bl[p][q + 2]);
                }
            // pass 3: lo*hi
#pragma unroll
            for (int mi = 0; mi < 4; mi++)
#pragma unroll
                for (int nt = 0; nt < 4; nt++) {
                    int p = nt >> 1, q = nt & 1;
                    mma_bf16(acc[mi][nt], al[mi], bh[p][q], bh[p][q + 2]);
                }
        }
    }

    // Epilogue
    const int g = lane >> 2, t4 = lane & 3;
    __nv_bfloat16 *dhi = nullptr, *dlo = nullptr;
    float oscl = 1.0f;
    if (mode == 0) {
        int w = blockIdx.z;
        dhi = (w == 0) ? g_qhi : (w == 1) ? g_khi : g_vhi;
        dlo = (w == 0) ? g_qlo : (w == 1) ? g_klo : g_vlo;
        // Q pre-scale: 1/sqrt(HD) * log2(e)  (softmax uses EX2 directly)
        if (w == 0) oscl = 0.125f * 1.44269504088896340736f;
    }
#pragma unroll
    for (int mi = 0; mi < 4; mi++)
#pragma unroll
        for (int nt = 0; nt < 4; nt++)
#pragma unroll
            for (int hf = 0; hf < 2; hf++) {
                int row = m0 + wm * 64 + 16 * mi + g + 8 * hf;
                int col = n0 + wn * 32 + 8 * nt + 2 * t4;
                float v0 = acc[mi][nt][2 * hf];
                float v1 = acc[mi][nt][2 * hf + 1];
                if (mode == 0) {
                    v0 *= oscl; v1 *= oscl;
                    int bb = row >> 11, s = row & (Sv - 1);
                    int hh = col >> 6, hd = col & 63;
                    size_t di = ((size_t)(bb * Hv + hh) * Sv + s) * HDv + hd;
                    uint32_t lo2;
                    uint32_t hi2 = split2(v0, v1, lo2);
                    *(uint32_t*)(dhi + di) = hi2;
                    *(uint32_t*)(dlo + di) = lo2;
                } else {
                    out[(size_t)row * Dv + col]     = v0 + bias[col];
                    out[(size_t)row * Dv + col + 1] = v1 + bias[col + 1];
                }
            }
}

// ---------------------------------------------------------------------------
// Tensor-core causal flash attention. BM=128, BN=64, 8 warps.
// Q pre-scaled by log2e/8; softmax via EX2 (base 2).
// Pass loop OUTSIDE in QK^T and PV for accumulator independence.
// ---------------------------------------------------------------------------
#define ATT_SMEM (96 * 1024)

__global__ __launch_bounds__(256, 2) void attn_tc()
{
    extern __shared__ char sm_[];
    uint32_t sb = smem_to_u32(sm_);
    const int tid = threadIdx.x, wid = tid >> 5, lane = tid & 31;
    const int qt = gridDim.x - 1 - blockIdx.x;   // big tiles first
    const int h = blockIdx.y, b = blockIdx.z;
    const int q0 = qt * 128;
    const size_t hb = (size_t)(b * Hv + h) * Sv * HDv;
    const __nv_bfloat16 *Qhi = g_qhi + hb, *Qlo = g_qlo + hb;
    const __nv_bfloat16 *Khi = g_khi + hb, *Klo = g_klo + hb;
    const __nv_bfloat16 *Vhi = g_vhi + hb, *Vlo = g_vlo + hb;

    // Q tiles via cp.async (128 rows x 8 units, hi+lo)
#pragma unroll
    for (int it = 0; it < 4; it++) {
        int idx = tid + it * 256;
        int row = idx >> 3, u = idx & 7;
        uint32_t so = swoff128(row, u);
        size_t gs = (size_t)(q0 + row) * HDv + u * 8;
        cp16(sb + so,         Qhi + gs);
        cp16(sb + 16384 + so, Qlo + gs);
    }
    CP_COMMIT();

    // Precomputed KV store offsets + source offsets
    const int kr0 = tid >> 3, ku0 = tid & 7;
    const int kr1 = (tid + 256) >> 3;
    const uint32_t kst0 = swoff128(kr0, ku0), kst1 = swoff128(kr1, ku0);
    const size_t ksrc0 = (size_t)kr0 * HDv + ku0 * 8;
    const size_t ksrc1 = (size_t)kr1 * HDv + ku0 * 8;

    auto issue_kv = [&](int kt, int stg) {
        uint32_t base = sb + 32768 + (uint32_t)stg * 32768;
        size_t adv = (size_t)kt * 64 * HDv;
        cp16(base + kst0,          Khi + adv + ksrc0);
        cp16(base + 8192 + kst0,   Klo + adv + ksrc0);
        cp16(base + 16384 + kst0,  Vhi + adv + ksrc0);
        cp16(base + 24576 + kst0,  Vlo + adv + ksrc0);
        cp16(base + kst1,          Khi + adv + ksrc1);
        cp16(base + 8192 + kst1,   Klo + adv + ksrc1);
        cp16(base + 16384 + kst1,  Vhi + adv + ksrc1);
        cp16(base + 24576 + kst1,  Vlo + adv + ksrc1);
        CP_COMMIT();
    };

    issue_kv(0, 0);

    const int lrow = lane & 15, lsel = lane >> 4, g = lane >> 2, t4 = lane & 3;

    // Precomputed ldmatrix offsets; k-step via XOR, V row-advance via +2048.
    const uint32_t q_off = swoff128(wid * 16 + lrow, lsel);
    uint32_t k_off[4], v_off[4];
#pragma unroll
    for (int p = 0; p < 4; p++) k_off[p] = swoff128(16 * p + lrow, lsel);
#pragma unroll
    for (int p2 = 0; p2 < 4; p2++) v_off[p2] = swoff128(lrow, 2 * p2 + lsel);

    float mreg[2] = {-1e30f, -1e30f}, lreg[2] = {0.f, 0.f};
    float o[8][4];
#pragma unroll
    for (int nt = 0; nt < 8; nt++)
#pragma unroll
        for (int k = 0; k < 4; k++) o[nt][k] = 0.f;

    const int gq0 = q0 + wid * 16 + g;
    const int gq1 = gq0 + 8;
    const int ntiles = 2 * qt + 2;

    for (int kt = 0; kt < ntiles; kt++) {
        CP_WAIT(0);
        __syncthreads();
        if (kt + 1 < ntiles) issue_kv(kt + 1, (kt + 1) & 1);

        uint32_t kvb = sb + 32768 + (uint32_t)(kt & 1) * 32768;
        const int k0r = kt * 64;

        // ---- S = Q K^T (3-pass hi/lo); scores already base-2 scaled ----
        float s[8][4];
#pragma unroll
        for (int nt = 0; nt < 8; nt++)
#pragma unroll
            for (int k = 0; k < 4; k++) s[nt][k] = 0.f;

#pragma unroll
        for (int ks = 0; ks < 4; ks++) {
            const uint32_t kso = (uint32_t)ks * 32u;
            uint32_t qh[4], ql[4];
            ldm_x4(qh, sb + (q_off ^ kso));
            ldm_x4(ql, sb + 16384 + (q_off ^ kso));
            uint32_t kh[4][4], kl[4][4];
#pragma unroll
            for (int p = 0; p < 4; p++) {
                ldm_x4(kh[p], kvb + (k_off[p] ^ kso));
                ldm_x4(kl[p], kvb + 8192 + (k_off[p] ^ kso));
            }
            // pass 1: qh*kh (8 independent accumulators)
#pragma unroll
            for (int nt = 0; nt < 8; nt++) {
                int p = nt >> 1, q = nt & 1;
                mma_bf16(s[nt], qh, kh[p][q], kh[p][q + 2]);
            }
            // pass 2: qh*kl
#pragma unroll
            for (int nt = 0; nt < 8; nt++) {
                int p = nt >> 1, q = nt & 1;
                mma_bf16(s[nt], qh, kl[p][q], kl[p][q + 2]);
            }
            // pass 3: ql*kh
#pragma unroll
            for (int nt = 0; nt < 8; nt++) {
                int p = nt >> 1, q = nt & 1;
                mma_bf16(s[nt], ql, kh[p][q], kh[p][q + 2]);
            }
        }

        // causal mask (only diagonal-region tiles)
        if (kt >= 2 * qt) {
#pragma unroll
            for (int nt = 0; nt < 8; nt++) {
                int c0 = k0r + 8 * nt + 2 * t4;
                if (c0 > gq0)     s[nt][0] = -1e30f;
                if (c0 + 1 > gq0) s[nt][1] = -1e30f;
                if (c0 > gq1)     s[nt][2] = -1e30f;
                if (c0 + 1 > gq1) s[nt][3] = -1e30f;
            }
        }

        // ---- online softmax (base 2, hardware EX2) ----
        float rm0 = -1e30f, rm1 = -1e30f;
#pragma unroll
        for (int nt = 0; nt < 8; nt++) {
            rm0 = fmaxf(rm0, fmaxf(s[nt][0], s[nt][1]));
            rm1 = fmaxf(rm1, fmaxf(s[nt][2], s[nt][3]));
        }
        rm0 = fmaxf(rm0, __shfl_xor_sync(0xffffffffu, rm0, 1));
        rm0 = fmaxf(rm0, __shfl_xor_sync(0xffffffffu, rm0, 2));
        rm1 = fmaxf(rm1, __shfl_xor_sync(0xffffffffu, rm1, 1));
        rm1 = fmaxf(rm1, __shfl_xor_sync(0xffffffffu, rm1, 2));

        float nm0 = fmaxf(mreg[0], rm0), nm1 = fmaxf(mreg[1], rm1);
        float a0 = ex2(mreg[0] - nm0), a1 = ex2(mreg[1] - nm1);
        mreg[0] = nm0; mreg[1] = nm1;

        float rs0 = 0.f, rs1 = 0.f;
#pragma unroll
        for (int nt = 0; nt < 8; nt++) {
            s[nt][0] = ex2(s[nt][0] - nm0);
            s[nt][1] = ex2(s[nt][1] - nm0);
            s[nt][2] = ex2(s[nt][2] - nm1);
            s[nt][3] = ex2(s[nt][3] - nm1);
            rs0 += s[nt][0] + s[nt][1];
            rs1 += s[nt][2] + s[nt][3];
        }
        rs0 += __shfl_xor_sync(0xffffffffu, rs0, 1);
        rs0 += __shfl_xor_sync(0xffffffffu, rs0, 2);
        rs1 += __shfl_xor_sync(0xffffffffu, rs1, 1);
        rs1 += __shfl_xor_sync(0xffffffffu, rs1, 2);
        lreg[0] = lreg[0] * a0 + rs0;
        lreg[1] = lreg[1] * a1 + rs1;

#pragma unroll
        for (int nt = 0; nt < 8; nt++) {
            o[nt][0] *= a0; o[nt][1] *= a0;
            o[nt][2] *= a1; o[nt][3] *= a1;
        }

        // ---- O += P V (3-pass, pass-outer ordering) ----
#pragma unroll
        for (int ks = 0; ks < 4; ks++) {
            const uint32_t vko = (uint32_t)ks * 2048u;
            uint32_t ph[4], pl[4];
            ph[0] = split2(s[2 * ks][0],     s[2 * ks][1],     pl[0]);
            ph[1] = split2(s[2 * ks][2],     s[2 * ks][3],     pl[1]);
            ph[2] = split2(s[2 * ks + 1][0], s[2 * ks + 1][1], pl[2]);
            ph[3] = split2(s[2 * ks + 1][2], s[2 * ks + 1][3], pl[3]);

            uint32_t vh[4][4], vl[4][4];
#pragma unroll
            for (int p2 = 0; p2 < 4; p2++) {
                ldm_x4_t(vh[p2], kvb + 16384 + v_off[p2] + vko);
                ldm_x4_t(vl[p2], kvb + 24576 + v_off[p2] + vko);
            }
            // pass 1: ph*vh
#pragma unroll
            for (int nt = 0; nt < 8; nt++) {
                int p2 = nt >> 1, q = nt & 1;
                mma_bf16(o[nt], ph, vh[p2][2 * q], vh[p2][2 * q + 1]);
            }
            // pass 2: pl*vh
#pragma unroll
            for (int nt = 0; nt < 8; nt++) {
                int p2 = nt >> 1, q = nt & 1;
                mma_bf16(o[nt], pl, vh[p2][2 * q], vh[p2][2 * q + 1]);
            }
            // pass 3: ph*vl
#pragma unroll
            for (int nt = 0; nt < 8; nt++) {
                int p2 = nt >> 1, q = nt & 1;
                mma_bf16(o[nt], ph, vl[p2][2 * q], vl[p2][2 * q + 1]);
            }
        }
    }

    // Epilogue: normalize, split hi/lo, write ctx [B*S, D]
    float inv0 = 1.f / lreg[0], inv1 = 1.f / lreg[1];
#pragma unroll
    for (int nt = 0; nt < 8; nt++) {
        int col = h * HDv + 8 * nt + 2 * t4;
        size_t r0 = ((size_t)b * Sv + gq0) * Dv + col;
        size_t r1 = ((size_t)b * Sv + gq1) * Dv + col;
        uint32_t lo2;
        uint32_t hi2 = split2(o[nt][0] * inv0, o[nt][1] * inv0, lo2);
        *(uint32_t*)(g_chi + r0) = hi2;
        *(uint32_t*)(g_clo + r0) = lo2;
        hi2 = split2(o[nt][2] * inv1, o[nt][3] * inv1, lo2);
        *(uint32_t*)(g_chi + r1) = hi2;
        *(uint32_t*)(g_clo + r1) = lo2;
    }
}

// ---------------------------------------------------------------------------
extern "C" void kernel_launch(void* const* d_in, const int* in_sizes, int n_in,
                              void* d_out, int out_size)
{
    const float* X  = (const float*)d_in[0];
    const float* Wq = (const float*)d_in[1];
    const float* Wk = (const float*)d_in[2];
    const float* Wv = (const float*)d_in[3];
    const float* Wo = (const float*)d_in[4];
    const float* bo = (const float*)d_in[5];
    float* out = (float*)d_out;

    cudaFuncSetAttribute(gemm_tc,
                         cudaFuncAttributeMaxDynamicSharedMemorySize, GEMM_SMEM);
    cudaFuncSetAttribute(attn_tc,
                         cudaFuncAttributeMaxDynamicSharedMemorySize, ATT_SMEM);

    const int nX4 = Mv * Dv / 4;
    const int nW4 = Dv * Dv / 4;

    cvt_x_kernel<<<nX4 / 256, 256>>>((const float4*)X);
    cvt_w_kernel<<<dim3(nW4 / 256, 4), 256>>>(
        (const float4*)Wq, (const float4*)Wk, (const float4*)Wv, (const float4*)Wo);

    gemm_tc<<<dim3(Dv / 128, Mv / 128, 3), 256, GEMM_SMEM>>>(0, nullptr, nullptr);

    attn_tc<<<dim3(Sv / 128, Hv, Bv), 256, ATT_SMEM>>>();

    gemm_tc<<<dim3(Dv / 128, Mv / 128, 1), 256, GEMM_SMEM>>>(1, out, bo);
}

// round 12
// speedup vs baseline: 1.8819x; 1.2156x over previous
#include <cuda_runtime.h>
#include <cuda_bf16.h>
#include <cuda_fp16.h>
#include <math.h>
#include <stdint.h>

// Problem constants
#define Bv 4
#define Sv 2048
#define Dv 1024
#define Hv 16
#define HDv 64
#define Mv (Bv * Sv)   // 8192 rows

// ---------------------------------------------------------------------------
// PTX helpers (sm_80+ baseline: mma.sync / ldmatrix / cp.async)
// ---------------------------------------------------------------------------
__device__ __forceinline__ uint32_t smem_to_u32(const void* p) {
    uint32_t a;
    asm("{ .reg .u64 t; cvta.to.shared.u64 t, %1; cvt.u32.u64 %0, t; }"
        : "=r"(a) : "l"(p));
    return a;
}

__device__ __forceinline__ void mma_bf16(float* c, const uint32_t* a,
                                         uint32_t b0, uint32_t b1) {
    asm volatile(
        "mma.sync.aligned.m16n8k16.row.col.f32.bf16.bf16.f32 "
        "{%0,%1,%2,%3}, {%4,%5,%6,%7}, {%8,%9}, {%0,%1,%2,%3};\n"
        : "+f"(c[0]), "+f"(c[1]), "+f"(c[2]), "+f"(c[3])
        : "r"(a[0]), "r"(a[1]), "r"(a[2]), "r"(a[3]), "r"(b0), "r"(b1));
}

__device__ __forceinline__ void mma_f16(float* c, const uint32_t* a,
                                        uint32_t b0, uint32_t b1) {
    asm volatile(
        "mma.sync.aligned.m16n8k16.row.col.f32.f16.f16.f32 "
        "{%0,%1,%2,%3}, {%4,%5,%6,%7}, {%8,%9}, {%0,%1,%2,%3};\n"
        : "+f"(c[0]), "+f"(c[1]), "+f"(c[2]), "+f"(c[3])
        : "r"(a[0]), "r"(a[1]), "r"(a[2]), "r"(a[3]), "r"(b0), "r"(b1));
}

__device__ __forceinline__ void ldm_x4(uint32_t* r, uint32_t a) {
    asm volatile("ldmatrix.sync.aligned.m8n8.x4.shared.b16 {%0,%1,%2,%3}, [%4];"
        : "=r"(r[0]), "=r"(r[1]), "=r"(r[2]), "=r"(r[3]) : "r"(a));
}
__device__ __forceinline__ void ldm_x4_t(uint32_t* r, uint32_t a) {
    asm volatile("ldmatrix.sync.aligned.m8n8.x4.trans.shared.b16 {%0,%1,%2,%3}, [%4];"
        : "=r"(r[0]), "=r"(r[1]), "=r"(r[2]), "=r"(r[3]) : "r"(a));
}

__device__ __forceinline__ void cp16(uint32_t dst, const void* src) {
    asm volatile("cp.async.cg.shared.global [%0], [%1], 16;"
        :: "r"(dst), "l"(src) : "memory");
}
#define CP_COMMIT() asm volatile("cp.async.commit_group;" ::: "memory")
#define CP_WAIT(N)  asm volatile("cp.async.wait_group %0;" :: "n"(N) : "memory")

// hardware EX2
__device__ __forceinline__ float ex2(float x) {
    float y;
    asm("ex2.approx.ftz.f32 %0, %1;" : "=f"(y) : "f"(x));
    return y;
}

// pack two floats into f16x2 (low = x, high = y)
__device__ __forceinline__ uint32_t pack_f16x2(float x, float y) {
    uint32_t r;
    asm("cvt.rn.f16x2.f32 %0, %1, %2;" : "=r"(r) : "f"(y), "f"(x));
    return r;
}

// swizzled byte offsets (computed once; k-steps advance via XOR)
__device__ __forceinline__ uint32_t swoff128(int row, int unit) {
    uint32_t off = (uint32_t)row * 128u + (uint32_t)unit * 16u;
    return off ^ ((off >> 3) & 0x70u);
}
__device__ __forceinline__ uint32_t swoff64(int row, int unit) {
    uint32_t off = (uint32_t)row * 64u + (uint32_t)unit * 16u;
    return off ^ ((off >> 3) & 0x30u);
}

// split float pair -> packed bf16x2 hi (returned) and lo (out param)
__device__ __forceinline__ uint32_t split2(float x, float y, uint32_t& lo) {
    __nv_bfloat16 hx = __float2bfloat16(x);
    __nv_bfloat16 hy = __float2bfloat16(y);
    __nv_bfloat162 hp(hx, hy);
    __nv_bfloat162 lp(__float2bfloat16(x - __bfloat162float(hx)),
                      __float2bfloat16(y - __bfloat162float(hy)));
    lo = *(uint32_t*)&lp;
    return *(uint32_t*)&hp;
}

// ---------------------------------------------------------------------------
// Scratch (allocation-guard-safe: __device__ globals)
// Q/K: single fp16; V: fp16 hi/lo; projections keep bf16 hi/lo
// ---------------------------------------------------------------------------
#define QKV_ELEMS ((size_t)Bv * Hv * Sv * HDv)
__device__ __half g_qh[QKV_ELEMS], g_kh[QKV_ELEMS];
__device__ __half g_vh[QKV_ELEMS], g_vl[QKV_ELEMS];
__device__ __nv_bfloat16 g_xhi[(size_t)Mv * Dv], g_xlo[(size_t)Mv * Dv];
__device__ __nv_bfloat16 g_whi[(size_t)4 * Dv * Dv], g_wlo[(size_t)4 * Dv * Dv];
__device__ __nv_bfloat16 g_chi[(size_t)Mv * Dv], g_clo[(size_t)Mv * Dv];

// ---------------------------------------------------------------------------
// fp32 -> bf16 hi/lo splits
// ---------------------------------------------------------------------------
__global__ __launch_bounds__(256) void cvt_x_kernel(const float4* __restrict__ src)
{
    int i = blockIdx.x * blockDim.x + threadIdx.x;
    float4 v = src[i];
    uint32_t l0, l1;
    uint32_t h0 = split2(v.x, v.y, l0);
    uint32_t h1 = split2(v.z, v.w, l1);
    uint32_t* hp = (uint32_t*)(g_xhi + (size_t)i * 4);
    uint32_t* lp = (uint32_t*)(g_xlo + (size_t)i * 4);
    hp[0] = h0; hp[1] = h1;
    lp[0] = l0; lp[1] = l1;
}

__global__ __launch_bounds__(256) void cvt_w_kernel(
    const float4* __restrict__ w0, const float4* __restrict__ w1,
    const float4* __restrict__ w2, const float4* __restrict__ w3)
{
    int i = blockIdx.x * blockDim.x + threadIdx.x;
    int w = blockIdx.y;
    const float4* src = (w == 0) ? w0 : (w == 1) ? w1 : (w == 2) ? w2 : w3;
    __nv_bfloat16* hi = g_whi + (size_t)w * Dv * Dv;
    __nv_bfloat16* lo = g_wlo + (size_t)w * Dv * Dv;
    float4 v = src[i];
    uint32_t l0, l1;
    uint32_t h0 = split2(v.x, v.y, l0);
    uint32_t h1 = split2(v.z, v.w, l1);
    uint32_t* hp = (uint32_t*)(hi + (size_t)i * 4);
    uint32_t* lp = (uint32_t*)(lo + (size_t)i * 4);
    hp[0] = h0; hp[1] = h1;
    lp[0] = l0; lp[1] = l1;
}

// ---------------------------------------------------------------------------
// Tensor-core GEMM: Out[M,N] = A[M,K] @ B[N,K]^T, bf16 hi/lo 3-pass, fp32 acc.
// Block 128x128, BK=32, 8 warps, 3-stage cp.async pipeline.
// mode 0 epilogue: w0->Q fp16 (scaled log2e/8), w1->K fp16, w2->V fp16 hi/lo
// mode 1 epilogue: fp32 out + bias
// ---------------------------------------------------------------------------
#define STG 32768
#define GEMM_SMEM (3 * STG)
#define NCH 32

__global__ __launch_bounds__(256, 2) void gemm_tc(
    int mode, float* __restrict__ out, const float* __restrict__ bias)
{
    extern __shared__ char smem[];
    uint32_t sb = smem_to_u32(smem);
    const int tid = threadIdx.x;
    const int wid = tid >> 5, lane = tid & 31;
    const int wm = wid & 1, wn = wid >> 1;
    const int m0 = blockIdx.y * 128, n0 = blockIdx.x * 128;

    const __nv_bfloat16 *Ahi, *Alo, *Bhi, *Blo;
    if (mode == 0) {
        int w = blockIdx.z;
        Ahi = g_xhi; Alo = g_xlo;
        Bhi = g_whi + (size_t)w * Dv * Dv;
        Blo = g_wlo + (size_t)w * Dv * Dv;
    } else {
        Ahi = g_chi; Alo = g_clo;
        Bhi = g_whi + (size_t)3 * Dv * Dv;
        Blo = g_wlo + (size_t)3 * Dv * Dv;
    }

    const int r0_ = tid >> 2, u0_ = tid & 3;
    const int r1_ = (tid + 256) >> 2;
    const uint32_t st0 = swoff64(r0_, u0_), st1 = swoff64(r1_, u0_);
    const size_t ga0 = (size_t)(m0 + r0_) * Dv + u0_ * 8;
    const size_t ga1 = (size_t)(m0 + r1_) * Dv + u0_ * 8;
    const size_t gb0 = (size_t)(n0 + r0_) * Dv + u0_ * 8;
    const size_t gb1 = (size_t)(n0 + r1_) * Dv + u0_ * 8;

    auto issue = [&](int ch, int stg) {
        uint32_t base = sb + (uint32_t)stg * STG;
        int k0 = ch * 32;
        cp16(base + st0,          Ahi + ga0 + k0);
        cp16(base + 8192 + st0,   Alo + ga0 + k0);
        cp16(base + 16384 + st0,  Bhi + gb0 + k0);
        cp16(base + 24576 + st0,  Blo + gb0 + k0);
        cp16(base + st1,          Ahi + ga1 + k0);
        cp16(base + 8192 + st1,   Alo + ga1 + k0);
        cp16(base + 16384 + st1,  Bhi + gb1 + k0);
        cp16(base + 24576 + st1,  Blo + gb1 + k0);
        CP_COMMIT();
    };

    float acc[4][4][4];
#pragma unroll
    for (int i = 0; i < 4; i++)
#pragma unroll
        for (int j = 0; j < 4; j++)
#pragma unroll
            for (int k = 0; k < 4; k++) acc[i][j][k] = 0.f;

    issue(0, 0);
    issue(1, 1);

    const int lrow = lane & 15, lsel = lane >> 4;

    uint32_t a_off[4], b_off[2];
#pragma unroll
    for (int mi = 0; mi < 4; mi++)
        a_off[mi] = swoff64(wm * 64 + 16 * mi + lrow, lsel);
#pragma unroll
    for (int p = 0; p < 2; p++)
        b_off[p] = swoff64(wn * 32 + 16 * p + lrow, lsel);

    for (int ch = 0; ch < NCH; ch++) {
        if (ch < NCH - 1) { CP_WAIT(1); } else { CP_WAIT(0); }
        __syncthreads();
        if (ch + 2 < NCH) issue(ch + 2, (ch + 2) % 3);

        uint32_t base = sb + (uint32_t)(ch % 3) * STG;
#pragma unroll
        for (int ks = 0; ks < 2; ks++) {
            const uint32_t kso = (uint32_t)ks * 32u;
            uint32_t ah[4][4], al[4][4], bh[2][4], bl[2][4];
#pragma unroll
            for (int mi = 0; mi < 4; mi++) {
                ldm_x4(ah[mi], base + (a_off[mi] ^ kso));
                ldm_x4(al[mi], base + 8192 + (a_off[mi] ^ kso));
            }
#pragma unroll
            for (int p = 0; p < 2; p++) {
                ldm_x4(bh[p], base + 16384 + (b_off[p] ^ kso));
                ldm_x4(bl[p], base + 24576 + (b_off[p] ^ kso));
            }
#pragma unroll
            for (int mi = 0; mi < 4; mi++)
#pragma unroll
                for (int nt = 0; nt < 4; nt++) {
                    int p = nt >> 1, q = nt & 1;
                    mma_bf16(acc[mi][nt], ah[mi], bh[p][q], bh[p][q + 2]);
                }
#pragma unroll
            for (int mi = 0; mi < 4; mi++)
#pragma unroll
                for (int nt = 0; nt < 4; nt++) {
                    int p = nt >> 1, q = nt & 1;
                    mma_bf16(acc[mi][nt], ah[mi], bl[p][q], bl[p][q + 2]);
                }
#pragma unroll
            for (int mi = 0; mi < 4; mi++)
#pragma unroll
                for (int nt = 0; nt < 4; nt++) {
                    int p = nt >> 1, q = nt & 1;
                    mma_bf16(acc[mi][nt], al[mi], bh[p][q], bh[p][q + 2]);
                }
        }
    }

    // Epilogue
    const int g = lane >> 2, t4 = lane & 3;
    const int w = (mode == 0) ? blockIdx.z : 3;
    // Q pre-scale: 1/sqrt(HD) * log2(e)  (softmax uses EX2 directly)
    const float oscl = (w == 0) ? 0.125f * 1.44269504088896340736f : 1.0f;
#pragma unroll
    for (int mi = 0; mi < 4; mi++)
#pragma unroll
        for (int nt = 0; nt < 4; nt++)
#pragma unroll
            for (int hf = 0; hf < 2; hf++) {
                int row = m0 + wm * 64 + 16 * mi + g + 8 * hf;
                int col = n0 + wn * 32 + 8 * nt + 2 * t4;
                float v0 = acc[mi][nt][2 * hf];
                float v1 = acc[mi][nt][2 * hf + 1];
                if (mode == 0) {
                    int bb = row >> 11, s = row & (Sv - 1);
                    int hh = col >> 6, hd = col & 63;
                    size_t di = ((size_t)(bb * Hv + hh) * Sv + s) * HDv + hd;
                    if (w == 0) {
                        *(uint32_t*)(g_qh + di) = pack_f16x2(v0 * oscl, v1 * oscl);
                    } else if (w == 1) {
                        *(uint32_t*)(g_kh + di) = pack_f16x2(v0, v1);
                    } else {
                        __half h0 = __float2half(v0), h1 = __float2half(v1);
                        __half l0 = __float2half(v0 - __half2float(h0));
                        __half l1 = __float2half(v1 - __half2float(h1));
                        __half2 hp(h0, h1), lp(l0, l1);
                        *(uint32_t*)(g_vh + di) = *(uint32_t*)&hp;
                        *(uint32_t*)(g_vl + di) = *(uint32_t*)&lp;
                    }
                } else {
                    out[(size_t)row * Dv + col]     = v0 + bias[col];
                    out[(size_t)row * Dv + col + 1] = v1 + bias[col + 1];
                }
            }
}

// ---------------------------------------------------------------------------
// Tensor-core causal flash attention. BM=128, BN=64, 8 warps.
// QK^T: single-pass fp16. PV: fp16 P x (Vhi + Vlo) 2-pass.
// smem: Q 16KB; KV stages (Kh,Vh,Vl = 24KB) x2 at +16384.
// ---------------------------------------------------------------------------
#define KVSTG 24576
#define ATT_SMEM (16384 + 2 * KVSTG)   // 65536

__global__ __launch_bounds__(256, 2) void attn_tc()
{
    extern __shared__ char sm_[];
    uint32_t sb = smem_to_u32(sm_);
    const int tid = threadIdx.x, wid = tid >> 5, lane = tid & 31;
    const int qt = gridDim.x - 1 - blockIdx.x;   // big tiles first
    const int h = blockIdx.y, b = blockIdx.z;
    const int q0 = qt * 128;
    const size_t hb = (size_t)(b * Hv + h) * Sv * HDv;
    const __half *Qh = g_qh + hb, *Kh = g_kh + hb;
    const __half *Vh = g_vh + hb, *Vl = g_vl + hb;

    // Q tile via cp.async (128 rows x 8 units, fp16 single)
#pragma unroll
    for (int it = 0; it < 4; it++) {
        int idx = tid + it * 256;
        int row = idx >> 3, u = idx & 7;
        cp16(sb + swoff128(row, u), Qh + (size_t)(q0 + row) * HDv + u * 8);
    }
    CP_COMMIT();

    // Precomputed KV store offsets + source offsets
    const int kr0 = tid >> 3, ku0 = tid & 7;
    const int kr1 = (tid + 256) >> 3;
    const uint32_t kst0 = swoff128(kr0, ku0), kst1 = swoff128(kr1, ku0);
    const size_t ksrc0 = (size_t)kr0 * HDv + ku0 * 8;
    const size_t ksrc1 = (size_t)kr1 * HDv + ku0 * 8;

    auto issue_kv = [&](int kt, int stg) {
        uint32_t base = sb + 16384 + (uint32_t)stg * KVSTG;
        size_t adv = (size_t)kt * 64 * HDv;
        cp16(base + kst0,          Kh + adv + ksrc0);
        cp16(base + 8192 + kst0,   Vh + adv + ksrc0);
        cp16(base + 16384 + kst0,  Vl + adv + ksrc0);
        cp16(base + kst1,          Kh + adv + ksrc1);
        cp16(base + 8192 + kst1,   Vh + adv + ksrc1);
        cp16(base + 16384 + kst1,  Vl + adv + ksrc1);
        CP_COMMIT();
    };

    issue_kv(0, 0);

    const int lrow = lane & 15, lsel = lane >> 4, g = lane >> 2, t4 = lane & 3;

    // Precomputed ldmatrix offsets; k-step via XOR, V row-advance via +2048.
    const uint32_t q_off = swoff128(wid * 16 + lrow, lsel);
    uint32_t k_off[4], v_off[4];
#pragma unroll
    for (int p = 0; p < 4; p++) k_off[p] = swoff128(16 * p + lrow, lsel);
#pragma unroll
    for (int p2 = 0; p2 < 4; p2++) v_off[p2] = swoff128(lrow, 2 * p2 + lsel);

    float mreg[2] = {-1e30f, -1e30f}, lreg[2] = {0.f, 0.f};
    float o[8][4];
#pragma unroll
    for (int nt = 0; nt < 8; nt++)
#pragma unroll
        for (int k = 0; k < 4; k++) o[nt][k] = 0.f;

    const int gq0 = q0 + wid * 16 + g;
    const int gq1 = gq0 + 8;
    const int ntiles = 2 * qt + 2;

    for (int kt = 0; kt < ntiles; kt++) {
        CP_WAIT(0);
        __syncthreads();
        if (kt + 1 < ntiles) issue_kv(kt + 1, (kt + 1) & 1);

        uint32_t kvb = sb + 16384 + (uint32_t)(kt & 1) * KVSTG;
        const int k0r = kt * 64;

        // ---- S = Q K^T (single-pass fp16); scores already base-2 scaled ----
        float s[8][4];
#pragma unroll
        for (int nt = 0; nt < 8; nt++)
#pragma unroll
            for (int k = 0; k < 4; k++) s[nt][k] = 0.f;

#pragma unroll
        for (int ks = 0; ks < 4; ks++) {
            const uint32_t kso = (uint32_t)ks * 32u;
            uint32_t qh[4];
            ldm_x4(qh, sb + (q_off ^ kso));
            uint32_t kh[4][4];
#pragma unroll
            for (int p = 0; p < 4; p++)
                ldm_x4(kh[p], kvb + (k_off[p] ^ kso));
#pragma unroll
            for (int nt = 0; nt < 8; nt++) {
                int p = nt >> 1, q = nt & 1;
                mma_f16(s[nt], qh, kh[p][q], kh[p][q + 2]);
            }
        }

        // causal mask (only diagonal-region tiles)
        if (kt >= 2 * qt) {
#pragma unroll
            for (int nt = 0; nt < 8; nt++) {
                int c0 = k0r + 8 * nt + 2 * t4;
                if (c0 > gq0)     s[nt][0] = -1e30f;
                if (c0 + 1 > gq0) s[nt][1] = -1e30f;
                if (c0 > gq1)     s[nt][2] = -1e30f;
                if (c0 + 1 > gq1) s[nt][3] = -1e30f;
            }
        }

        // ---- online softmax (base 2, hardware EX2) ----
        float rm0 = -1e30f, rm1 = -1e30f;
#pragma unroll
        for (int nt = 0; nt < 8; nt++) {
            rm0 = fmaxf(rm0, fmaxf(s[nt][0], s[nt][1]));
            rm1 = fmaxf(rm1, fmaxf(s[nt][2], s[nt][3]));
        }
        rm0 = fmaxf(rm0, __shfl_xor_sync(0xffffffffu, rm0, 1));
        rm0 = fmaxf(rm0, __shfl_xor_sync(0xffffffffu, rm0, 2));
        rm1 = fmaxf(rm1, __shfl_xor_sync(0xffffffffu, rm1, 1));
        rm1 = fmaxf(rm1, __shfl_xor_sync(0xffffffffu, rm1, 2));

        float nm0 = fmaxf(mreg[0], rm0), nm1 = fmaxf(mreg[1], rm1);
        float a0 = ex2(mreg[0] - nm0), a1 = ex2(mreg[1] - nm1);
        mreg[0] = nm0; mreg[1] = nm1;

        float rs0 = 0.f, rs1 = 0.f;
#pragma unroll
        for (int nt = 0; nt < 8; nt++) {
            s[nt][0] = ex2(s[nt][0] - nm0);
            s[nt][1] = ex2(s[nt][1] - nm0);
            s[nt][2] = ex2(s[nt][2] - nm1);
            s[nt][3] = ex2(s[nt][3] - nm1);
            rs0 += s[nt][0] + s[nt][1];
            rs1 += s[nt][2] + s[nt][3];
        }
        rs0 += __shfl_xor_sync(0xffffffffu, rs0, 1);
        rs0 += __shfl_xor_sync(0xffffffffu, rs0, 2);
        rs1 += __shfl_xor_sync(0xffffffffu, rs1, 1);
        rs1 += __shfl_xor_sync(0xffffffffu, rs1, 2);
        lreg[0] = lreg[0] * a0 + rs0;
        lreg[1] = lreg[1] * a1 + rs1;

#pragma unroll
        for (int nt = 0; nt < 8; nt++) {
            o[nt][0] *= a0; o[nt][1] *= a0;
            o[nt][2] *= a1; o[nt][3] *= a1;
        }

        // ---- O += P V (fp16 P, 2-pass: P*Vh + P*Vl) ----
#pragma unroll
        for (int ks = 0; ks < 4; ks++) {
            const uint32_t vko = (uint32_t)ks * 2048u;
            uint32_t ph[4];
            ph[0] = pack_f16x2(s[2 * ks][0],     s[2 * ks][1]);
            ph[1] = pack_f16x2(s[2 * ks][2],     s[2 * ks][3]);
            ph[2] = pack_f16x2(s[2 * ks + 1][0], s[2 * ks + 1][1]);
            ph[3] = pack_f16x2(s[2 * ks + 1][2], s[2 * ks + 1][3]);

            uint32_t vh[4][4], vl[4][4];
#pragma unroll
            for (int p2 = 0; p2 < 4; p2++) {
                ldm_x4_t(vh[p2], kvb + 8192 + v_off[p2] + vko);
                ldm_x4_t(vl[p2], kvb + 16384 + v_off[p2] + vko);
            }
#pragma unroll
            for (int nt = 0; nt < 8; nt++) {
                int p2 = nt >> 1, q = nt & 1;
                mma_f16(o[nt], ph, vh[p2][2 * q], vh[p2][2 * q + 1]);
            }
#pragma unroll
            for (int nt = 0; nt < 8; nt++) {
                int p2 = nt >> 1, q = nt & 1;
                mma_f16(o[nt], ph, vl[p2][2 * q], vl[p2][2 * q + 1]);
            }
        }
    }

    // Epilogue: normalize, split hi/lo (bf16 for O-proj), write ctx [B*S, D]
    float inv0 = 1.f / lreg[0], inv1 = 1.f / lreg[1];
#pragma unroll
    for (int nt = 0; nt < 8; nt++) {
        int col = h * HDv + 8 * nt + 2 * t4;
        size_t r0 = ((size_t)b * Sv + gq0) * Dv + col;
        size_t r1 = ((size_t)b * Sv + gq1) * Dv + col;
        uint32_t lo2;
        uint32_t hi2 = split2(o[nt][0] * inv0, o[nt][1] * inv0, lo2);
        *(uint32_t*)(g_chi + r0) = hi2;
        *(uint32_t*)(g_clo + r0) = lo2;
        hi2 = split2(o[nt][2] * inv1, o[nt][3] * inv1, lo2);
        *(uint32_t*)(g_chi + r1) = hi2;
        *(uint32_t*)(g_clo + r1) = lo2;
    }
}

// ---------------------------------------------------------------------------
extern "C" void kernel_launch(void* const* d_in, const int* in_sizes, int n_in,
                              void* d_out, int out_size)
{
    const float* X  = (const float*)d_in[0];
    const float* Wq = (const float*)d_in[1];
    const float* Wk = (const float*)d_in[2];
    const float* Wv = (const float*)d_in[3];
    const float* Wo = (const float*)d_in[4];
    const float* bo = (const float*)d_in[5];
    float* out = (float*)d_out;

    cudaFuncSetAttribute(gemm_tc,
                         cudaFuncAttributeMaxDynamicSharedMemorySize, GEMM_SMEM);
    cudaFuncSetAttribute(attn_tc,
                         cudaFuncAttributeMaxDynamicSharedMemorySize, ATT_SMEM);

    const int nX4 = Mv * Dv / 4;
    const int nW4 = Dv * Dv / 4;

    cvt_x_kernel<<<nX4 / 256, 256>>>((const float4*)X);
    cvt_w_kernel<<<dim3(nW4 / 256, 4), 256>>>(
        (const float4*)Wq, (const float4*)Wk, (const float4*)Wv, (const float4*)Wo);

    gemm_tc<<<dim3(Dv / 128, Mv / 128, 3), 256, GEMM_SMEM>>>(0, nullptr, nullptr);

    attn_tc<<<dim3(Sv / 128, Hv, Bv), 256, ATT_SMEM>>>();

    gemm_tc<<<dim3(Dv / 128, Mv / 128, 1), 256, GEMM_SMEM>>>(1, out, bo);
}

// round 13
// speedup vs baseline: 2.7266x; 1.4488x over previous
#include <cuda_runtime.h>
#include <cuda_bf16.h>
#include <cuda_fp16.h>
#include <math.h>
#include <stdint.h>

// Problem constants
#define Bv 4
#define Sv 2048
#define Dv 1024
#define Hv 16
#define HDv 64
#define Mv (Bv * Sv)   // 8192 rows

// ---------------------------------------------------------------------------
// PTX helpers (sm_80+ baseline: mma.sync / ldmatrix / cp.async)
// ---------------------------------------------------------------------------
__device__ __forceinline__ uint32_t smem_to_u32(const void* p) {
    uint32_t a;
    asm("{ .reg .u64 t; cvta.to.shared.u64 t, %1; cvt.u32.u64 %0, t; }"
        : "=r"(a) : "l"(p));
    return a;
}

__device__ __forceinline__ void mma_f16(float* c, const uint32_t* a,
                                        uint32_t b0, uint32_t b1) {
    asm volatile(
        "mma.sync.aligned.m16n8k16.row.col.f32.f16.f16.f32 "
        "{%0,%1,%2,%3}, {%4,%5,%6,%7}, {%8,%9}, {%0,%1,%2,%3};\n"
        : "+f"(c[0]), "+f"(c[1]), "+f"(c[2]), "+f"(c[3])
        : "r"(a[0]), "r"(a[1]), "r"(a[2]), "r"(a[3]), "r"(b0), "r"(b1));
}

__device__ __forceinline__ void ldm_x4(uint32_t* r, uint32_t a) {
    asm volatile("ldmatrix.sync.aligned.m8n8.x4.shared.b16 {%0,%1,%2,%3}, [%4];"
        : "=r"(r[0]), "=r"(r[1]), "=r"(r[2]), "=r"(r[3]) : "r"(a));
}
__device__ __forceinline__ void ldm_x4_t(uint32_t* r, uint32_t a) {
    asm volatile("ldmatrix.sync.aligned.m8n8.x4.trans.shared.b16 {%0,%1,%2,%3}, [%4];"
        : "=r"(r[0]), "=r"(r[1]), "=r"(r[2]), "=r"(r[3]) : "r"(a));
}

__device__ __forceinline__ void cp16(uint32_t dst, const void* src) {
    asm volatile("cp.async.cg.shared.global [%0], [%1], 16;"
        :: "r"(dst), "l"(src) : "memory");
}
#define CP_COMMIT() asm volatile("cp.async.commit_group;" ::: "memory")
#define CP_WAIT(N)  asm volatile("cp.async.wait_group %0;" :: "n"(N) : "memory")

// hardware EX2
__device__ __forceinline__ float ex2(float x) {
    float y;
    asm("ex2.approx.ftz.f32 %0, %1;" : "=f"(y) : "f"(x));
    return y;
}

// pack two floats into f16x2 (low = x, high = y)
__device__ __forceinline__ uint32_t pack_f16x2(float x, float y) {
    uint32_t r;
    asm("cvt.rn.f16x2.f32 %0, %1, %2;" : "=r"(r) : "f"(y), "f"(x));
    return r;
}

// fp16 hi/lo split of a float pair -> packed hi (returned) and lo (out)
__device__ __forceinline__ uint32_t splith2(float x, float y, uint32_t& lo) {
    __half hx = __float2half(x);
    __half hy = __float2half(y);
    __half2 hp(hx, hy);
    __half2 lp(__float2half(x - __half2float(hx)),
               __float2half(y - __half2float(hy)));
    lo = *(uint32_t*)&lp;
    return *(uint32_t*)&hp;
}

// swizzled byte offsets (computed once; k-steps advance via XOR)
__device__ __forceinline__ uint32_t swoff128(int row, int unit) {
    uint32_t off = (uint32_t)row * 128u + (uint32_t)unit * 16u;
    return off ^ ((off >> 3) & 0x70u);
}
__device__ __forceinline__ uint32_t swoff64(int row, int unit) {
    uint32_t off = (uint32_t)row * 64u + (uint32_t)unit * 16u;
    return off ^ ((off >> 3) & 0x30u);
}

// ---------------------------------------------------------------------------
// Scratch (allocation-guard-safe: __device__ globals)
// Activations single fp16; weights fp16 hi/lo.
// ---------------------------------------------------------------------------
#define QKV_ELEMS ((size_t)Bv * Hv * Sv * HDv)
__device__ __half g_qh[QKV_ELEMS], g_kh[QKV_ELEMS], g_vh[QKV_ELEMS];
__device__ __half g_xh[(size_t)Mv * Dv];
__device__ __half g_wh[(size_t)4 * Dv * Dv], g_wl[(size_t)4 * Dv * Dv];
__device__ __half g_ch[(size_t)Mv * Dv];

// ---------------------------------------------------------------------------
// fp32 -> fp16 conversions
// ---------------------------------------------------------------------------
__global__ __launch_bounds__(256) void cvt_x_kernel(const float4* __restrict__ src)
{
    int i = blockIdx.x * blockDim.x + threadIdx.x;
    float4 v = src[i];
    uint32_t* p = (uint32_t*)(g_xh + (size_t)i * 4);
    p[0] = pack_f16x2(v.x, v.y);
    p[1] = pack_f16x2(v.z, v.w);
}

__global__ __launch_bounds__(256) void cvt_w_kernel(
    const float4* __restrict__ w0, const float4* __restrict__ w1,
    const float4* __restrict__ w2, const float4* __restrict__ w3)
{
    int i = blockIdx.x * blockDim.x + threadIdx.x;
    int w = blockIdx.y;
    const float4* src = (w == 0) ? w0 : (w == 1) ? w1 : (w == 2) ? w2 : w3;
    __half* hi = g_wh + (size_t)w * Dv * Dv;
    __half* lo = g_wl + (size_t)w * Dv * Dv;
    float4 v = src[i];
    uint32_t l0, l1;
    uint32_t h0 = splith2(v.x, v.y, l0);
    uint32_t h1 = splith2(v.z, v.w, l1);
    uint32_t* hp = (uint32_t*)(hi + (size_t)i * 4);
    uint32_t* lp = (uint32_t*)(lo + (size_t)i * 4);
    hp[0] = h0; hp[1] = h1;
    lp[0] = l0; lp[1] = l1;
}

// ---------------------------------------------------------------------------
// Tensor-core GEMM: Out[M,N] = A[M,K] @ B[N,K]^T.
// A single fp16, B fp16 hi/lo 2-pass, fp32 acc.
// Block 128x128, BK=32, 8 warps (warp tile 64x32), 3-stage cp.async pipeline.
// mode 0 epilogue: w0->Q fp16 (scaled log2e/8), w1->K fp16, w2->V fp16
// mode 1 epilogue: fp32 out + bias
// ---------------------------------------------------------------------------
#define STG 24576                    // A 8KB + Bh 8KB + Bl 8KB
#define GEMM_SMEM (3 * STG)          // 72 KB
#define NCH 32

__global__ __launch_bounds__(256, 2) void gemm_tc(
    int mode, float* __restrict__ out, const float* __restrict__ bias)
{
    extern __shared__ char smem[];
    uint32_t sb = smem_to_u32(smem);
    const int tid = threadIdx.x;
    const int wid = tid >> 5, lane = tid & 31;
    const int wm = wid & 1, wn = wid >> 1;
    const int m0 = blockIdx.y * 128, n0 = blockIdx.x * 128;

    const __half *Ah, *Bh, *Bl;
    if (mode == 0) {
        int w = blockIdx.z;
        Ah = g_xh;
        Bh = g_wh + (size_t)w * Dv * Dv;
        Bl = g_wl + (size_t)w * Dv * Dv;
    } else {
        Ah = g_ch;
        Bh = g_wh + (size_t)3 * Dv * Dv;
        Bl = g_wl + (size_t)3 * Dv * Dv;
    }

    const int r0_ = tid >> 2, u0_ = tid & 3;
    const int r1_ = (tid + 256) >> 2;
    const uint32_t st0 = swoff64(r0_, u0_), st1 = swoff64(r1_, u0_);
    const size_t ga0 = (size_t)(m0 + r0_) * Dv + u0_ * 8;
    const size_t ga1 = (size_t)(m0 + r1_) * Dv + u0_ * 8;
    const size_t gb0 = (size_t)(n0 + r0_) * Dv + u0_ * 8;
    const size_t gb1 = (size_t)(n0 + r1_) * Dv + u0_ * 8;

    auto issue = [&](int ch, int stg) {
        uint32_t base = sb + (uint32_t)stg * STG;
        int k0 = ch * 32;
        cp16(base + st0,          Ah + ga0 + k0);
        cp16(base + st1,          Ah + ga1 + k0);
        cp16(base + 8192 + st0,   Bh + gb0 + k0);
        cp16(base + 8192 + st1,   Bh + gb1 + k0);
        cp16(base + 16384 + st0,  Bl + gb0 + k0);
        cp16(base + 16384 + st1,  Bl + gb1 + k0);
        CP_COMMIT();
    };

    float acc[4][4][4];
#pragma unroll
    for (int i = 0; i < 4; i++)
#pragma unroll
        for (int j = 0; j < 4; j++)
#pragma unroll
            for (int k = 0; k < 4; k++) acc[i][j][k] = 0.f;

    issue(0, 0);
    issue(1, 1);

    const int lrow = lane & 15, lsel = lane >> 4;

    uint32_t a_off[4], b_off[2];
#pragma unroll
    for (int mi = 0; mi < 4; mi++)
        a_off[mi] = swoff64(wm * 64 + 16 * mi + lrow, lsel);
#pragma unroll
    for (int p = 0; p < 2; p++)
        b_off[p] = swoff64(wn * 32 + 16 * p + lrow, lsel);

    for (int ch = 0; ch < NCH; ch++) {
        if (ch < NCH - 1) { CP_WAIT(1); } else { CP_WAIT(0); }
        __syncthreads();
        if (ch + 2 < NCH) issue(ch + 2, (ch + 2) % 3);

        uint32_t base = sb + (uint32_t)(ch % 3) * STG;
#pragma unroll
        for (int ks = 0; ks < 2; ks++) {
            const uint32_t kso = (uint32_t)ks * 32u;
            uint32_t ah[4][4], bh[2][4], bl[2][4];
#pragma unroll
            for (int mi = 0; mi < 4; mi++)
                ldm_x4(ah[mi], base + (a_off[mi] ^ kso));
#pragma unroll
            for (int p = 0; p < 2; p++) {
                ldm_x4(bh[p], base + 8192 + (b_off[p] ^ kso));
                ldm_x4(bl[p], base + 16384 + (b_off[p] ^ kso));
            }
            // pass 1: a * Wh
#pragma unroll
            for (int mi = 0; mi < 4; mi++)
#pragma unroll
                for (int nt = 0; nt < 4; nt++) {
                    int p = nt >> 1, q = nt & 1;
                    mma_f16(acc[mi][nt], ah[mi], bh[p][q], bh[p][q + 2]);
                }
            // pass 2: a * Wl
#pragma unroll
            for (int mi = 0; mi < 4; mi++)
#pragma unroll
                for (int nt = 0; nt < 4; nt++) {
                    int p = nt >> 1, q = nt & 1;
                    mma_f16(acc[mi][nt], ah[mi], bl[p][q], bl[p][q + 2]);
                }
        }
    }

    // Epilogue
    const int g = lane >> 2, t4 = lane & 3;
    const int w = (mode == 0) ? blockIdx.z : 3;
    // Q pre-scale: 1/sqrt(HD) * log2(e)  (softmax uses EX2 directly)
    const float oscl = (w == 0) ? 0.125f * 1.44269504088896340736f : 1.0f;
#pragma unroll
    for (int mi = 0; mi < 4; mi++)
#pragma unroll
        for (int nt = 0; nt < 4; nt++)
#pragma unroll
            for (int hf = 0; hf < 2; hf++) {
                int row = m0 + wm * 64 + 16 * mi + g + 8 * hf;
                int col = n0 + wn * 32 + 8 * nt + 2 * t4;
                float v0 = acc[mi][nt][2 * hf];
                float v1 = acc[mi][nt][2 * hf + 1];
                if (mode == 0) {
                    int bb = row >> 11, s = row & (Sv - 1);
                    int hh = col >> 6, hd = col & 63;
                    size_t di = ((size_t)(bb * Hv + hh) * Sv + s) * HDv + hd;
                    __half* dst = (w == 0) ? g_qh : (w == 1) ? g_kh : g_vh;
                    *(uint32_t*)(dst + di) = pack_f16x2(v0 * oscl, v1 * oscl);
                } else {
                    out[(size_t)row * Dv + col]     = v0 + bias[col];
                    out[(size_t)row * Dv + col + 1] = v1 + bias[col + 1];
                }
            }
}

// ---------------------------------------------------------------------------
// Tensor-core causal flash attention. BM=128, BN=64, 8 warps.
// QK^T: single-pass fp16. PV: single-pass fp16.
// smem: Q 16KB; KV stages (Kh,Vh = 16KB) x2 at +16384.
// ---------------------------------------------------------------------------
#define KVSTG 16384
#define ATT_SMEM (16384 + 2 * KVSTG)   // 49152

__global__ __launch_bounds__(256, 2) void attn_tc()
{
    extern __shared__ char sm_[];
    uint32_t sb = smem_to_u32(sm_);
    const int tid = threadIdx.x, wid = tid >> 5, lane = tid & 31;
    const int qt = gridDim.x - 1 - blockIdx.x;   // big tiles first
    const int h = blockIdx.y, b = blockIdx.z;
    const int q0 = qt * 128;
    const size_t hb = (size_t)(b * Hv + h) * Sv * HDv;
    const __half *Qh = g_qh + hb, *Kh = g_kh + hb, *Vh = g_vh + hb;

    // Q tile via cp.async (128 rows x 8 units, fp16 single)
#pragma unroll
    for (int it = 0; it < 4; it++) {
        int idx = tid + it * 256;
        int row = idx >> 3, u = idx & 7;
        cp16(sb + swoff128(row, u), Qh + (size_t)(q0 + row) * HDv + u * 8);
    }
    CP_COMMIT();

    // Precomputed KV store offsets + source offsets
    const int kr0 = tid >> 3, ku0 = tid & 7;
    const int kr1 = (tid + 256) >> 3;
    const uint32_t kst0 = swoff128(kr0, ku0), kst1 = swoff128(kr1, ku0);
    const size_t ksrc0 = (size_t)kr0 * HDv + ku0 * 8;
    const size_t ksrc1 = (size_t)kr1 * HDv + ku0 * 8;

    auto issue_kv = [&](int kt, int stg) {
        uint32_t base = sb + 16384 + (uint32_t)stg * KVSTG;
        size_t adv = (size_t)kt * 64 * HDv;
        cp16(base + kst0,         Kh + adv + ksrc0);
        cp16(base + 8192 + kst0,  Vh + adv + ksrc0);
        cp16(base + kst1,         Kh + adv + ksrc1);
        cp16(base + 8192 + kst1,  Vh + adv + ksrc1);
        CP_COMMIT();
    };

    issue_kv(0, 0);

    const int lrow = lane & 15, lsel = lane >> 4, g = lane >> 2, t4 = lane & 3;

    // Precomputed ldmatrix offsets; k-step via XOR, V row-advance via +2048.
    const uint32_t q_off = swoff128(wid * 16 + lrow, lsel);
    uint32_t k_off[4], v_off[4];
#pragma unroll
    for (int p = 0; p < 4; p++) k_off[p] = swoff128(16 * p + lrow, lsel);
#pragma unroll
    for (int p2 = 0; p2 < 4; p2++) v_off[p2] = swoff128(lrow, 2 * p2 + lsel);

    float mreg[2] = {-1e30f, -1e30f}, lreg[2] = {0.f, 0.f};
    float o[8][4];
#pragma unroll
    for (int nt = 0; nt < 8; nt++)
#pragma unroll
        for (int k = 0; k < 4; k++) o[nt][k] = 0.f;

    const int gq0 = q0 + wid * 16 + g;
    const int gq1 = gq0 + 8;
    const int ntiles = 2 * qt + 2;

    for (int kt = 0; kt < ntiles; kt++) {
        CP_WAIT(0);
        __syncthreads();
        if (kt + 1 < ntiles) issue_kv(kt + 1, (kt + 1) & 1);

        uint32_t kvb = sb + 16384 + (uint32_t)(kt & 1) * KVSTG;
        const int k0r = kt * 64;

        // ---- S = Q K^T (single-pass fp16); scores already base-2 scaled ----
        float s[8][4];
#pragma unroll
        for (int nt = 0; nt < 8; nt++)
#pragma unroll
            for (int k = 0; k < 4; k++) s[nt][k] = 0.f;

#pragma unroll
        for (int ks = 0; ks < 4; ks++) {
            const uint32_t kso = (uint32_t)ks * 32u;
            uint32_t qh[4];
            ldm_x4(qh, sb + (q_off ^ kso));
            uint32_t kh[4][4];
#pragma unroll
            for (int p = 0; p < 4; p++)
                ldm_x4(kh[p], kvb + (k_off[p] ^ kso));
#pragma unroll
            for (int nt = 0; nt < 8; nt++) {
                int p = nt >> 1, q = nt & 1;
                mma_f16(s[nt], qh, kh[p][q], kh[p][q + 2]);
            }
        }

        // causal mask (only diagonal-region tiles)
        if (kt >= 2 * qt) {
#pragma unroll
            for (int nt = 0; nt < 8; nt++) {
                int c0 = k0r + 8 * nt + 2 * t4;
                if (c0 > gq0)     s[nt][0] = -1e30f;
                if (c0 + 1 > gq0) s[nt][1] = -1e30f;
                if (c0 > gq1)     s[nt][2] = -1e30f;
                if (c0 + 1 > gq1) s[nt][3] = -1e30f;
            }
        }

        // ---- online softmax (base 2, hardware EX2) ----
        float rm0 = -1e30f, rm1 = -1e30f;
#pragma unroll
        for (int nt = 0; nt < 8; nt++) {
            rm0 = fmaxf(rm0, fmaxf(s[nt][0], s[nt][1]));
            rm1 = fmaxf(rm1, fmaxf(s[nt][2], s[nt][3]));
        }
        rm0 = fmaxf(rm0, __shfl_xor_sync(0xffffffffu, rm0, 1));
        rm0 = fmaxf(rm0, __shfl_xor_sync(0xffffffffu, rm0, 2));
        rm1 = fmaxf(rm1, __shfl_xor_sync(0xffffffffu, rm1, 1));
        rm1 = fmaxf(rm1, __shfl_xor_sync(0xffffffffu, rm1, 2));

        float nm0 = fmaxf(mreg[0], rm0), nm1 = fmaxf(mreg[1], rm1);
        float a0 = ex2(mreg[0] - nm0), a1 = ex2(mreg[1] - nm1);
        mreg[0] = nm0; mreg[1] = nm1;

        float rs0 = 0.f, rs1 = 0.f;
#pragma unroll
        for (int nt = 0; nt < 8; nt++) {
            s[nt][0] = ex2(s[nt][0] - nm0);
            s[nt][1] = ex2(s[nt][1] - nm0);
            s[nt][2] = ex2(s[nt][2] - nm1);
            s[nt][3] = ex2(s[nt][3] - nm1);
            rs0 += s[nt][0] + s[nt][1];
            rs1 += s[nt][2] + s[nt][3];
        }
        rs0 += __shfl_xor_sync(0xffffffffu, rs0, 1);
        rs0 += __shfl_xor_sync(0xffffffffu, rs0, 2);
        rs1 += __shfl_xor_sync(0xffffffffu, rs1, 1);
        rs1 += __shfl_xor_sync(0xffffffffu, rs1, 2);
        lreg[0] = lreg[0] * a0 + rs0;
        lreg[1] = lreg[1] * a1 + rs1;

#pragma unroll
        for (int nt = 0; nt < 8; nt++) {
            o[nt][0] *= a0; o[nt][1] *= a0;
            o[nt][2] *= a1; o[nt][3] *= a1;
        }

        // ---- O += P V (fp16 P, single pass) ----
#pragma unroll
        for (int ks = 0; ks < 4; ks++) {
            const uint32_t vko = (uint32_t)ks * 2048u;
            uint32_t ph[4];
            ph[0] = pack_f16x2(s[2 * ks][0],     s[2 * ks][1]);
            ph[1] = pack_f16x2(s[2 * ks][2],     s[2 * ks][3]);
            ph[2] = pack_f16x2(s[2 * ks + 1][0], s[2 * ks + 1][1]);
            ph[3] = pack_f16x2(s[2 * ks + 1][2], s[2 * ks + 1][3]);

            uint32_t vh[4][4];
#pragma unroll
            for (int p2 = 0; p2 < 4; p2++)
                ldm_x4_t(vh[p2], kvb + 8192 + v_off[p2] + vko);
#pragma unroll
            for (int nt = 0; nt < 8; nt++) {
                int p2 = nt >> 1, q = nt & 1;
                mma_f16(o[nt], ph, vh[p2][2 * q], vh[p2][2 * q + 1]);
            }
        }
    }

    // Epilogue: normalize, write ctx fp16 [B*S, D]
    float inv0 = 1.f / lreg[0], inv1 = 1.f / lreg[1];
#pragma unroll
    for (int nt = 0; nt < 8; nt++) {
        int col = h * HDv + 8 * nt + 2 * t4;
        size_t r0 = ((size_t)b * Sv + gq0) * Dv + col;
        size_t r1 = ((size_t)b * Sv + gq1) * Dv + col;
        *(uint32_t*)(g_ch + r0) = pack_f16x2(o[nt][0] * inv0, o[nt][1] * inv0);
        *(uint32_t*)(g_ch + r1) = pack_f16x2(o[nt][2] * inv1, o[nt][3] * inv1);
    }
}

// ---------------------------------------------------------------------------
extern "C" void kernel_launch(void* const* d_in, const int* in_sizes, int n_in,
                              void* d_out, int out_size)
{
    const float* X  = (const float*)d_in[0];
    const float* Wq = (const float*)d_in[1];
    const float* Wk = (const float*)d_in[2];
    const float* Wv = (const float*)d_in[3];
    const float* Wo = (const float*)d_in[4];
    const float* bo = (const float*)d_in[5];
    float* out = (float*)d_out;

    cudaFuncSetAttribute(gemm_tc,
                         cudaFuncAttributeMaxDynamicSharedMemorySize, GEMM_SMEM);
    cudaFuncSetAttribute(attn_tc,
                         cudaFuncAttributeMaxDynamicSharedMemorySize, ATT_SMEM);

    const int nX4 = Mv * Dv / 4;
    const int nW4 = Dv * Dv / 4;

    cvt_x_kernel<<<nX4 / 256, 256>>>((const float4*)X);
    cvt_w_kernel<<<dim3(nW4 / 256, 4), 256>>>(
        (const float4*)Wq, (const float4*)Wk, (const float4*)Wv, (const float4*)Wo);

    gemm_tc<<<dim3(Dv / 128, Mv / 128, 3), 256, GEMM_SMEM>>>(0, nullptr, nullptr);

    attn_tc<<<dim3(Sv / 128, Hv, Bv), 256, ATT_SMEM>>>();

    gemm_tc<<<dim3(Dv / 128, Mv / 128, 1), 256, GEMM_SMEM>>>(1, out, bo);
}

// round 14
// speedup vs baseline: 3.7777x; 1.3855x over previous
#include <cuda_runtime.h>
#include <cuda_fp16.h>
#include <math.h>
#include <stdint.h>

// Problem constants
#define Bv 4
#define Sv 2048
#define Dv 1024
#define Hv 16
#define HDv 64
#define Mv (Bv * Sv)   // 8192 rows

// ---------------------------------------------------------------------------
// PTX helpers (sm_80+ baseline: mma.sync / ldmatrix / cp.async)
// ---------------------------------------------------------------------------
__device__ __forceinline__ uint32_t smem_to_u32(const void* p) {
    uint32_t a;
    asm("{ .reg .u64 t; cvta.to.shared.u64 t, %1; cvt.u32.u64 %0, t; }"
        : "=r"(a) : "l"(p));
    return a;
}

__device__ __forceinline__ void mma_f16(float* c, const uint32_t* a,
                                        uint32_t b0, uint32_t b1) {
    asm volatile(
        "mma.sync.aligned.m16n8k16.row.col.f32.f16.f16.f32 "
        "{%0,%1,%2,%3}, {%4,%5,%6,%7}, {%8,%9}, {%0,%1,%2,%3};\n"
        : "+f"(c[0]), "+f"(c[1]), "+f"(c[2]), "+f"(c[3])
        : "r"(a[0]), "r"(a[1]), "r"(a[2]), "r"(a[3]), "r"(b0), "r"(b1));
}

__device__ __forceinline__ void ldm_x4(uint32_t* r, uint32_t a) {
    asm volatile("ldmatrix.sync.aligned.m8n8.x4.shared.b16 {%0,%1,%2,%3}, [%4];"
        : "=r"(r[0]), "=r"(r[1]), "=r"(r[2]), "=r"(r[3]) : "r"(a));
}
__device__ __forceinline__ void ldm_x4_t(uint32_t* r, uint32_t a) {
    asm volatile("ldmatrix.sync.aligned.m8n8.x4.trans.shared.b16 {%0,%1,%2,%3}, [%4];"
        : "=r"(r[0]), "=r"(r[1]), "=r"(r[2]), "=r"(r[3]) : "r"(a));
}

__device__ __forceinline__ void cp16(uint32_t dst, const void* src) {
    asm volatile("cp.async.cg.shared.global [%0], [%1], 16;"
        :: "r"(dst), "l"(src) : "memory");
}
#define CP_COMMIT() asm volatile("cp.async.commit_group;" ::: "memory")
#define CP_WAIT(N)  asm volatile("cp.async.wait_group %0;" :: "n"(N) : "memory")

// hardware EX2
__device__ __forceinline__ float ex2(float x) {
    float y;
    asm("ex2.approx.ftz.f32 %0, %1;" : "=f"(y) : "f"(x));
    return y;
}

// pack two floats into f16x2 (low = x, high = y)
__device__ __forceinline__ uint32_t pack_f16x2(float x, float y) {
    uint32_t r;
    asm("cvt.rn.f16x2.f32 %0, %1, %2;" : "=r"(r) : "f"(y), "f"(x));
    return r;
}

// swizzled byte offsets (computed once; k-steps advance via XOR)
__device__ __forceinline__ uint32_t swoff128(int row, int unit) {
    uint32_t off = (uint32_t)row * 128u + (uint32_t)unit * 16u;
    return off ^ ((off >> 3) & 0x70u);
}
__device__ __forceinline__ uint32_t swoff64(int row, int unit) {
    uint32_t off = (uint32_t)row * 64u + (uint32_t)unit * 16u;
    return off ^ ((off >> 3) & 0x30u);
}

// ---------------------------------------------------------------------------
// Scratch (allocation-guard-safe: __device__ globals); all single fp16
// ---------------------------------------------------------------------------
#define QKV_ELEMS ((size_t)Bv * Hv * Sv * HDv)
__device__ __half g_qh[QKV_ELEMS], g_kh[QKV_ELEMS], g_vh[QKV_ELEMS];
__device__ __half g_xh[(size_t)Mv * Dv];
__device__ __half g_wh[(size_t)4 * Dv * Dv];
__device__ __half g_ch[(size_t)Mv * Dv];

// ---------------------------------------------------------------------------
// fp32 -> fp16 conversions
// ---------------------------------------------------------------------------
__global__ __launch_bounds__(256) void cvt_x_kernel(const float4* __restrict__ src)
{
    int i = blockIdx.x * blockDim.x + threadIdx.x;
    float4 v = src[i];
    uint32_t* p = (uint32_t*)(g_xh + (size_t)i * 4);
    p[0] = pack_f16x2(v.x, v.y);
    p[1] = pack_f16x2(v.z, v.w);
}

__global__ __launch_bounds__(256) void cvt_w_kernel(
    const float4* __restrict__ w0, const float4* __restrict__ w1,
    const float4* __restrict__ w2, const float4* __restrict__ w3)
{
    int i = blockIdx.x * blockDim.x + threadIdx.x;
    int w = blockIdx.y;
    const float4* src = (w == 0) ? w0 : (w == 1) ? w1 : (w == 2) ? w2 : w3;
    __half* hi = g_wh + (size_t)w * Dv * Dv;
    float4 v = src[i];
    uint32_t* hp = (uint32_t*)(hi + (size_t)i * 4);
    hp[0] = pack_f16x2(v.x, v.y);
    hp[1] = pack_f16x2(v.z, v.w);
}

// ---------------------------------------------------------------------------
// Tensor-core GEMM: Out[M,N] = A[M,K] @ B[N,K]^T, single-pass fp16, fp32 acc.
// Block 128x128, BK=32, 8 warps (warp tile 64x32), 3-stage cp.async pipeline.
// mode 0 epilogue: w0->Q fp16 (scaled log2e/8), w1->K fp16, w2->V fp16
// mode 1 epilogue: fp32 out + bias
// ---------------------------------------------------------------------------
#define STG 16384                    // A 8KB + B 8KB
#define GEMM_SMEM (3 * STG)          // 48 KB
#define NCH 32

__global__ __launch_bounds__(256, 2) void gemm_tc(
    int mode, float* __restrict__ out, const float* __restrict__ bias)
{
    extern __shared__ char smem[];
    uint32_t sb = smem_to_u32(smem);
    const int tid = threadIdx.x;
    const int wid = tid >> 5, lane = tid & 31;
    const int wm = wid & 1, wn = wid >> 1;
    const int m0 = blockIdx.y * 128, n0 = blockIdx.x * 128;

    const __half *Ah, *Bh;
    if (mode == 0) {
        int w = blockIdx.z;
        Ah = g_xh;
        Bh = g_wh + (size_t)w * Dv * Dv;
    } else {
        Ah = g_ch;
        Bh = g_wh + (size_t)3 * Dv * Dv;
    }

    const int r0_ = tid >> 2, u0_ = tid & 3;
    const int r1_ = (tid + 256) >> 2;
    const uint32_t st0 = swoff64(r0_, u0_), st1 = swoff64(r1_, u0_);
    const size_t ga0 = (size_t)(m0 + r0_) * Dv + u0_ * 8;
    const size_t ga1 = (size_t)(m0 + r1_) * Dv + u0_ * 8;
    const size_t gb0 = (size_t)(n0 + r0_) * Dv + u0_ * 8;
    const size_t gb1 = (size_t)(n0 + r1_) * Dv + u0_ * 8;

    auto issue = [&](int ch, int stg) {
        uint32_t base = sb + (uint32_t)stg * STG;
        int k0 = ch * 32;
        cp16(base + st0,         Ah + ga0 + k0);
        cp16(base + st1,         Ah + ga1 + k0);
        cp16(base + 8192 + st0,  Bh + gb0 + k0);
        cp16(base + 8192 + st1,  Bh + gb1 + k0);
        CP_COMMIT();
    };

    float acc[4][4][4];
#pragma unroll
    for (int i = 0; i < 4; i++)
#pragma unroll
        for (int j = 0; j < 4; j++)
#pragma unroll
            for (int k = 0; k < 4; k++) acc[i][j][k] = 0.f;

    issue(0, 0);
    issue(1, 1);

    const int lrow = lane & 15, lsel = lane >> 4;

    uint32_t a_off[4], b_off[2];
#pragma unroll
    for (int mi = 0; mi < 4; mi++)
        a_off[mi] = swoff64(wm * 64 + 16 * mi + lrow, lsel);
#pragma unroll
    for (int p = 0; p < 2; p++)
        b_off[p] = swoff64(wn * 32 + 16 * p + lrow, lsel);

    for (int ch = 0; ch < NCH; ch++) {
        if (ch < NCH - 1) { CP_WAIT(1); } else { CP_WAIT(0); }
        __syncthreads();
        if (ch + 2 < NCH) issue(ch + 2, (ch + 2) % 3);

        uint32_t base = sb + (uint32_t)(ch % 3) * STG;
#pragma unroll
        for (int ks = 0; ks < 2; ks++) {
            const uint32_t kso = (uint32_t)ks * 32u;
            uint32_t ah[4][4], bh[2][4];
#pragma unroll
            for (int mi = 0; mi < 4; mi++)
                ldm_x4(ah[mi], base + (a_off[mi] ^ kso));
#pragma unroll
            for (int p = 0; p < 2; p++)
                ldm_x4(bh[p], base + 8192 + (b_off[p] ^ kso));
#pragma unroll
            for (int mi = 0; mi < 4; mi++)
#pragma unroll
                for (int nt = 0; nt < 4; nt++) {
                    int p = nt >> 1, q = nt & 1;
                    mma_f16(acc[mi][nt], ah[mi], bh[p][q], bh[p][q + 2]);
                }
        }
    }

    // Epilogue
    const int g = lane >> 2, t4 = lane & 3;
    const int w = (mode == 0) ? blockIdx.z : 3;
    // Q pre-scale: 1/sqrt(HD) * log2(e)  (softmax uses EX2 directly)
    const float oscl = (w == 0) ? 0.125f * 1.44269504088896340736f : 1.0f;
#pragma unroll
    for (int mi = 0; mi < 4; mi++)
#pragma unroll
        for (int nt = 0; nt < 4; nt++)
#pragma unroll
            for (int hf = 0; hf < 2; hf++) {
                int row = m0 + wm * 64 + 16 * mi + g + 8 * hf;
                int col = n0 + wn * 32 + 8 * nt + 2 * t4;
                float v0 = acc[mi][nt][2 * hf];
                float v1 = acc[mi][nt][2 * hf + 1];
                if (mode == 0) {
                    int bb = row >> 11, s = row & (Sv - 1);
                    int hh = col >> 6, hd = col & 63;
                    size_t di = ((size_t)(bb * Hv + hh) * Sv + s) * HDv + hd;
                    __half* dst = (w == 0) ? g_qh : (w == 1) ? g_kh : g_vh;
                    *(uint32_t*)(dst + di) = pack_f16x2(v0 * oscl, v1 * oscl);
                } else {
                    out[(size_t)row * Dv + col]     = v0 + bias[col];
                    out[(size_t)row * Dv + col + 1] = v1 + bias[col + 1];
                }
            }
}

// ---------------------------------------------------------------------------
// Tensor-core causal flash attention. BM=128, BN=64, 8 warps.
// QK^T: single-pass fp16. PV: single-pass fp16. (unchanged from R12)
// smem: Q 16KB; KV stages (Kh,Vh = 16KB) x2 at +16384.
// ---------------------------------------------------------------------------
#define KVSTG 16384
#define ATT_SMEM (16384 + 2 * KVSTG)   // 49152

__global__ __launch_bounds__(256, 2) void attn_tc()
{
    extern __shared__ char sm_[];
    uint32_t sb = smem_to_u32(sm_);
    const int tid = threadIdx.x, wid = tid >> 5, lane = tid & 31;
    const int qt = gridDim.x - 1 - blockIdx.x;   // big tiles first
    const int h = blockIdx.y, b = blockIdx.z;
    const int q0 = qt * 128;
    const size_t hb = (size_t)(b * Hv + h) * Sv * HDv;
    const __half *Qh = g_qh + hb, *Kh = g_kh + hb, *Vh = g_vh + hb;

    // Q tile via cp.async (128 rows x 8 units, fp16 single)
#pragma unroll
    for (int it = 0; it < 4; it++) {
        int idx = tid + it * 256;
        int row = idx >> 3, u = idx & 7;
        cp16(sb + swoff128(row, u), Qh + (size_t)(q0 + row) * HDv + u * 8);
    }
    CP_COMMIT();

    // Precomputed KV store offsets + source offsets
    const int kr0 = tid >> 3, ku0 = tid & 7;
    const int kr1 = (tid + 256) >> 3;
    const uint32_t kst0 = swoff128(kr0, ku0), kst1 = swoff128(kr1, ku0);
    const size_t ksrc0 = (size_t)kr0 * HDv + ku0 * 8;
    const size_t ksrc1 = (size_t)kr1 * HDv + ku0 * 8;

    auto issue_kv = [&](int kt, int stg) {
        uint32_t base = sb + 16384 + (uint32_t)stg * KVSTG;
        size_t adv = (size_t)kt * 64 * HDv;
        cp16(base + kst0,         Kh + adv + ksrc0);
        cp16(base + 8192 + kst0,  Vh + adv + ksrc0);
        cp16(base + kst1,         Kh + adv + ksrc1);
        cp16(base + 8192 + kst1,  Vh + adv + ksrc1);
        CP_COMMIT();
    };

    issue_kv(0, 0);

    const int lrow = lane & 15, lsel = lane >> 4, g = lane >> 2, t4 = lane & 3;

    // Precomputed ldmatrix offsets; k-step via XOR, V row-advance via +2048.
    const uint32_t q_off = swoff128(wid * 16 + lrow, lsel);
    uint32_t k_off[4], v_off[4];
#pragma unroll
    for (int p = 0; p < 4; p++) k_off[p] = swoff128(16 * p + lrow, lsel);
#pragma unroll
    for (int p2 = 0; p2 < 4; p2++) v_off[p2] = swoff128(lrow, 2 * p2 + lsel);

    float mreg[2] = {-1e30f, -1e30f}, lreg[2] = {0.f, 0.f};
    float o[8][4];
#pragma unroll
    for (int nt = 0; nt < 8; nt++)
#pragma unroll
        for (int k = 0; k < 4; k++) o[nt][k] = 0.f;

    const int gq0 = q0 + wid * 16 + g;
    const int gq1 = gq0 + 8;
    const int ntiles = 2 * qt + 2;

    for (int kt = 0; kt < ntiles; kt++) {
        CP_WAIT(0);
        __syncthreads();
        if (kt + 1 < ntiles) issue_kv(kt + 1, (kt + 1) & 1);

        uint32_t kvb = sb + 16384 + (uint32_t)(kt & 1) * KVSTG;
        const int k0r = kt * 64;

        // ---- S = Q K^T (single-pass fp16); scores already base-2 scaled ----
        float s[8][4];
#pragma unroll
        for (int nt = 0; nt < 8; nt++)
#pragma unroll
            for (int k = 0; k < 4; k++) s[nt][k] = 0.f;

#pragma unroll
        for (int ks = 0; ks < 4; ks++) {
            const uint32_t kso = (uint32_t)ks * 32u;
            uint32_t qh[4];
            ldm_x4(qh, sb + (q_off ^ kso));
            uint32_t kh[4][4];
#pragma unroll
            for (int p = 0; p < 4; p++)
                ldm_x4(kh[p], kvb + (k_off[p] ^ kso));
#pragma unroll
            for (int nt = 0; nt < 8; nt++) {
                int p = nt >> 1, q = nt & 1;
                mma_f16(s[nt], qh, kh[p][q], kh[p][q + 2]);
            }
        }

        // causal mask (only diagonal-region tiles)
        if (kt >= 2 * qt) {
#pragma unroll
            for (int nt = 0; nt < 8; nt++) {
                int c0 = k0r + 8 * nt + 2 * t4;
                if (c0 > gq0)     s[nt][0] = -1e30f;
                if (c0 + 1 > gq0) s[nt][1] = -1e30f;
                if (c0 > gq1)     s[nt][2] = -1e30f;
                if (c0 + 1 > gq1) s[nt][3] = -1e30f;
            }
        }

        // ---- online softmax (base 2, hardware EX2) ----
        float rm0 = -1e30f, rm1 = -1e30f;
#pragma unroll
        for (int nt = 0; nt < 8; nt++) {
            rm0 = fmaxf(rm0, fmaxf(s[nt][0], s[nt][1]));
            rm1 = fmaxf(rm1, fmaxf(s[nt][2], s[nt][3]));
        }
        rm0 = fmaxf(rm0, __shfl_xor_sync(0xffffffffu, rm0, 1));
        rm0 = fmaxf(rm0, __shfl_xor_sync(0xffffffffu, rm0, 2));
        rm1 = fmaxf(rm1, __shfl_xor_sync(0xffffffffu, rm1, 1));
        rm1 = fmaxf(rm1, __shfl_xor_sync(0xffffffffu, rm1, 2));

        float nm0 = fmaxf(mreg[0], rm0), nm1 = fmaxf(mreg[1], rm1);
        float a0 = ex2(mreg[0] - nm0), a1 = ex2(mreg[1] - nm1);
        mreg[0] = nm0; mreg[1] = nm1;

        float rs0 = 0.f, rs1 = 0.f;
#pragma unroll
        for (int nt = 0; nt < 8; nt++) {
            s[nt][0] = ex2(s[nt][0] - nm0);
            s[nt][1] = ex2(s[nt][1] - nm0);
            s[nt][2] = ex2(s[nt][2] - nm1);
            s[nt][3] = ex2(s[nt][3] - nm1);
            rs0 += s[nt][0] + s[nt][1];
            rs1 += s[nt][2] + s[nt][3];
        }
        rs0 += __shfl_xor_sync(0xffffffffu, rs0, 1);
        rs0 += __shfl_xor_sync(0xffffffffu, rs0, 2);
        rs1 += __shfl_xor_sync(0xffffffffu, rs1, 1);
        rs1 += __shfl_xor_sync(0xffffffffu, rs1, 2);
        lreg[0] = lreg[0] * a0 + rs0;
        lreg[1] = lreg[1] * a1 + rs1;

#pragma unroll
        for (int nt = 0; nt < 8; nt++) {
            o[nt][0] *= a0; o[nt][1] *= a0;
            o[nt][2] *= a1; o[nt][3] *= a1;
        }

        // ---- O += P V (fp16 P, single pass) ----
#pragma unroll
        for (int ks = 0; ks < 4; ks++) {
            const uint32_t vko = (uint32_t)ks * 2048u;
            uint32_t ph[4];
            ph[0] = pack_f16x2(s[2 * ks][0],     s[2 * ks][1]);
            ph[1] = pack_f16x2(s[2 * ks][2],     s[2 * ks][3]);
            ph[2] = pack_f16x2(s[2 * ks + 1][0], s[2 * ks + 1][1]);
            ph[3] = pack_f16x2(s[2 * ks + 1][2], s[2 * ks + 1][3]);

            uint32_t vh[4][4];
#pragma unroll
            for (int p2 = 0; p2 < 4; p2++)
                ldm_x4_t(vh[p2], kvb + 8192 + v_off[p2] + vko);
#pragma unroll
            for (int nt = 0; nt < 8; nt++) {
                int p2 = nt >> 1, q = nt & 1;
                mma_f16(o[nt], ph, vh[p2][2 * q], vh[p2][2 * q + 1]);
            }
        }
    }

    // Epilogue: normalize, write ctx fp16 [B*S, D]
    float inv0 = 1.f / lreg[0], inv1 = 1.f / lreg[1];
#pragma unroll
    for (int nt = 0; nt < 8; nt++) {
        int col = h * HDv + 8 * nt + 2 * t4;
        size_t r0 = ((size_t)b * Sv + gq0) * Dv + col;
        size_t r1 = ((size_t)b * Sv + gq1) * Dv + col;
        *(uint32_t*)(g_ch + r0) = pack_f16x2(o[nt][0] * inv0, o[nt][1] * inv0);
        *(uint32_t*)(g_ch + r1) = pack_f16x2(o[nt][2] * inv1, o[nt][3] * inv1);
    }
}

// ---------------------------------------------------------------------------
extern "C" void kernel_launch(void* const* d_in, const int* in_sizes, int n_in,
                              void* d_out, int out_size)
{
    const float* X  = (const float*)d_in[0];
    const float* Wq = (const float*)d_in[1];
    const float* Wk = (const float*)d_in[2];
    const float* Wv = (const float*)d_in[3];
    const float* Wo = (const float*)d_in[4];
    const float* bo = (const float*)d_in[5];
    float* out = (float*)d_out;

    cudaFuncSetAttribute(gemm_tc,
                         cudaFuncAttributeMaxDynamicSharedMemorySize, GEMM_SMEM);
    cudaFuncSetAttribute(attn_tc,
                         cudaFuncAttributeMaxDynamicSharedMemorySize, ATT_SMEM);

    const int nX4 = Mv * Dv / 4;
    const int nW4 = Dv * Dv / 4;

    cvt_x_kernel<<<nX4 / 256, 256>>>((const float4*)X);
    cvt_w_kernel<<<dim3(nW4 / 256, 4), 256>>>(
        (const float4*)Wq, (const float4*)Wk, (const float4*)Wv, (const float4*)Wo);

    gemm_tc<<<dim3(Dv / 128, Mv / 128, 3), 256, GEMM_SMEM>>>(0, nullptr, nullptr);

    attn_tc<<<dim3(Sv / 128, Hv, Bv), 256, ATT_SMEM>>>();

    gemm_tc<<<dim3(Dv / 128, Mv / 128, 1), 256, GEMM_SMEM>>>(1, out, bo);
}

// round 15
// speedup vs baseline: 3.8894x; 1.0296x over previous
#include <cuda_runtime.h>
#include <cuda_fp16.h>
#include <math.h>
#include <stdint.h>

// Problem constants
#define Bv 4
#define Sv 2048
#define Dv 1024
#define Hv 16
#define HDv 64
#define Mv (Bv * Sv)   // 8192 rows

// ---------------------------------------------------------------------------
// PTX helpers (sm_80+ baseline: mma.sync / ldmatrix / cp.async)
// ---------------------------------------------------------------------------
__device__ __forceinline__ uint32_t smem_to_u32(const void* p) {
    uint32_t a;
    asm("{ .reg .u64 t; cvta.to.shared.u64 t, %1; cvt.u32.u64 %0, t; }"
        : "=r"(a) : "l"(p));
    return a;
}

__device__ __forceinline__ void mma_f16(float* c, const uint32_t* a,
                                        uint32_t b0, uint32_t b1) {
    asm volatile(
        "mma.sync.aligned.m16n8k16.row.col.f32.f16.f16.f32 "
        "{%0,%1,%2,%3}, {%4,%5,%6,%7}, {%8,%9}, {%0,%1,%2,%3};\n"
        : "+f"(c[0]), "+f"(c[1]), "+f"(c[2]), "+f"(c[3])
        : "r"(a[0]), "r"(a[1]), "r"(a[2]), "r"(a[3]), "r"(b0), "r"(b1));
}

__device__ __forceinline__ void ldm_x4(uint32_t* r, uint32_t a) {
    asm volatile("ldmatrix.sync.aligned.m8n8.x4.shared.b16 {%0,%1,%2,%3}, [%4];"
        : "=r"(r[0]), "=r"(r[1]), "=r"(r[2]), "=r"(r[3]) : "r"(a));
}
__device__ __forceinline__ void ldm_x4_t(uint32_t* r, uint32_t a) {
    asm volatile("ldmatrix.sync.aligned.m8n8.x4.trans.shared.b16 {%0,%1,%2,%3}, [%4];"
        : "=r"(r[0]), "=r"(r[1]), "=r"(r[2]), "=r"(r[3]) : "r"(a));
}

__device__ __forceinline__ void cp16(uint32_t dst, const void* src) {
    asm volatile("cp.async.cg.shared.global [%0], [%1], 16;"
        :: "r"(dst), "l"(src) : "memory");
}
#define CP_COMMIT() asm volatile("cp.async.commit_group;" ::: "memory")
#define CP_WAIT(N)  asm volatile("cp.async.wait_group %0;" :: "n"(N) : "memory")

// hardware EX2 (fp32) and paired fp16x2 EX2
__device__ __forceinline__ float ex2(float x) {
    float y;
    asm("ex2.approx.ftz.f32 %0, %1;" : "=f"(y) : "f"(x));
    return y;
}
__device__ __forceinline__ uint32_t h2ex2(uint32_t x) {
    uint32_t y;
    asm("ex2.approx.f16x2 %0, %1;" : "=r"(y) : "r"(x));
    return y;
}

// pack two floats into f16x2 (low = x, high = y)
__device__ __forceinline__ uint32_t pack_f16x2(float x, float y) {
    uint32_t r;
    asm("cvt.rn.f16x2.f32 %0, %1, %2;" : "=r"(r) : "f"(y), "f"(x));
    return r;
}

// fp16x2 constant 1.0, 1.0
#define ONES_H2 0x3C003C00u

// swizzled byte offsets (computed once; k-steps advance via XOR)
__device__ __forceinline__ uint32_t swoff128(int row, int unit) {
    uint32_t off = (uint32_t)row * 128u + (uint32_t)unit * 16u;
    return off ^ ((off >> 3) & 0x70u);
}

// ---------------------------------------------------------------------------
// Scratch (allocation-guard-safe: __device__ globals); all single fp16
// ---------------------------------------------------------------------------
#define QKV_ELEMS ((size_t)Bv * Hv * Sv * HDv)
__device__ __half g_qh[QKV_ELEMS], g_kh[QKV_ELEMS], g_vh[QKV_ELEMS];
__device__ __half g_xh[(size_t)Mv * Dv];
__device__ __half g_wh[(size_t)4 * Dv * Dv];
__device__ __half g_ch[(size_t)Mv * Dv];

// ---------------------------------------------------------------------------
// fp32 -> fp16 conversions
// ---------------------------------------------------------------------------
__global__ __launch_bounds__(256) void cvt_x_kernel(const float4* __restrict__ src)
{
    int i = blockIdx.x * blockDim.x + threadIdx.x;
    float4 v = src[i];
    uint32_t* p = (uint32_t*)(g_xh + (size_t)i * 4);
    p[0] = pack_f16x2(v.x, v.y);
    p[1] = pack_f16x2(v.z, v.w);
}

__global__ __launch_bounds__(256) void cvt_w_kernel(
    const float4* __restrict__ w0, const float4* __restrict__ w1,
    const float4* __restrict__ w2, const float4* __restrict__ w3)
{
    int i = blockIdx.x * blockDim.x + threadIdx.x;
    int w = blockIdx.y;
    const float4* src = (w == 0) ? w0 : (w == 1) ? w1 : (w == 2) ? w2 : w3;
    __half* hi = g_wh + (size_t)w * Dv * Dv;
    float4 v = src[i];
    uint32_t* hp = (uint32_t*)(hi + (size_t)i * 4);
    hp[0] = pack_f16x2(v.x, v.y);
    hp[1] = pack_f16x2(v.z, v.w);
}

// ---------------------------------------------------------------------------
// Tensor-core GEMM: Out[M,N] = A[M,K] @ B[N,K]^T, single-pass fp16, fp32 acc.
// Block 128x128, BK=64 (128B rows, swoff128), 8 warps, 3-stage cp.async.
// mode 0 epilogue: w0->Q fp16 (scaled log2e/8), w1->K fp16, w2->V fp16
// mode 1 epilogue: fp32 out + bias
// ---------------------------------------------------------------------------
#define STG 32768                    // A 16KB + B 16KB
#define GEMM_SMEM (3 * STG)          // 96 KB -> 2 CTAs/SM
#define NCH 16

__global__ __launch_bounds__(256, 2) void gemm_tc(
    int mode, float* __restrict__ out, const float* __restrict__ bias)
{
    extern __shared__ char smem[];
    uint32_t sb = smem_to_u32(smem);
    const int tid = threadIdx.x;
    const int wid = tid >> 5, lane = tid & 31;
    const int wm = wid & 1, wn = wid >> 1;
    const int m0 = blockIdx.y * 128, n0 = blockIdx.x * 128;

    const __half *Ah, *Bh;
    if (mode == 0) {
        int w = blockIdx.z;
        Ah = g_xh;
        Bh = g_wh + (size_t)w * Dv * Dv;
    } else {
        Ah = g_ch;
        Bh = g_wh + (size_t)3 * Dv * Dv;
    }

    // Precomputed cp.async store offsets + gmem source offsets (4 per thread)
    uint32_t kst[4];
    size_t asrc[4], bsrc[4];
#pragma unroll
    for (int it = 0; it < 4; it++) {
        int idx = tid + it * 256;       // 0..1023
        int row = idx >> 3, u = idx & 7;
        kst[it] = swoff128(row, u);
        asrc[it] = (size_t)(m0 + row) * Dv + u * 8;
        bsrc[it] = (size_t)(n0 + row) * Dv + u * 8;
    }

    auto issue = [&](int ch, int stg) {
        uint32_t base = sb + (uint32_t)stg * STG;
        int k0 = ch * 64;
#pragma unroll
        for (int it = 0; it < 4; it++) {
            cp16(base + kst[it],         Ah + asrc[it] + k0);
            cp16(base + 16384 + kst[it], Bh + bsrc[it] + k0);
        }
        CP_COMMIT();
    };

    float acc[4][4][4];
#pragma unroll
    for (int i = 0; i < 4; i++)
#pragma unroll
        for (int j = 0; j < 4; j++)
#pragma unroll
            for (int k = 0; k < 4; k++) acc[i][j][k] = 0.f;

    issue(0, 0);
    issue(1, 1);

    const int lrow = lane & 15, lsel = lane >> 4;

    // ldmatrix offsets at unit=lsel (offset bits 5-6 clear):
    // swizzled(off + ks*32) == swizzled(off) ^ (ks*32)
    uint32_t a_off[4], b_off[2];
#pragma unroll
    for (int mi = 0; mi < 4; mi++)
        a_off[mi] = swoff128(wm * 64 + 16 * mi + lrow, lsel);
#pragma unroll
    for (int p = 0; p < 2; p++)
        b_off[p] = swoff128(wn * 32 + 16 * p + lrow, lsel);

    for (int ch = 0; ch < NCH; ch++) {
        if (ch < NCH - 1) { CP_WAIT(1); } else { CP_WAIT(0); }
        __syncthreads();
        if (ch + 2 < NCH) issue(ch + 2, (ch + 2) % 3);

        uint32_t base = sb + (uint32_t)(ch % 3) * STG;
#pragma unroll
        for (int ks = 0; ks < 4; ks++) {
            const uint32_t kso = (uint32_t)ks * 32u;
            uint32_t ah[4][4], bh[2][4];
#pragma unroll
            for (int mi = 0; mi < 4; mi++)
                ldm_x4(ah[mi], base + (a_off[mi] ^ kso));
#pragma unroll
            for (int p = 0; p < 2; p++)
                ldm_x4(bh[p], base + 16384 + (b_off[p] ^ kso));
#pragma unroll
            for (int mi = 0; mi < 4; mi++)
#pragma unroll
                for (int nt = 0; nt < 4; nt++) {
                    int p = nt >> 1, q = nt & 1;
                    mma_f16(acc[mi][nt], ah[mi], bh[p][q], bh[p][q + 2]);
                }
        }
    }

    // Epilogue
    const int g = lane >> 2, t4 = lane & 3;
    const int w = (mode == 0) ? blockIdx.z : 3;
    // Q pre-scale: 1/sqrt(HD) * log2(e)  (softmax uses EX2 directly)
    const float oscl = (w == 0) ? 0.125f * 1.44269504088896340736f : 1.0f;
#pragma unroll
    for (int mi = 0; mi < 4; mi++)
#pragma unroll
        for (int nt = 0; nt < 4; nt++)
#pragma unroll
            for (int hf = 0; hf < 2; hf++) {
                int row = m0 + wm * 64 + 16 * mi + g + 8 * hf;
                int col = n0 + wn * 32 + 8 * nt + 2 * t4;
                float v0 = acc[mi][nt][2 * hf];
                float v1 = acc[mi][nt][2 * hf + 1];
                if (mode == 0) {
                    int bb = row >> 11, s = row & (Sv - 1);
                    int hh = col >> 6, hd = col & 63;
                    size_t di = ((size_t)(bb * Hv + hh) * Sv + s) * HDv + hd;
                    __half* dst = (w == 0) ? g_qh : (w == 1) ? g_kh : g_vh;
                    *(uint32_t*)(dst + di) = pack_f16x2(v0 * oscl, v1 * oscl);
                } else {
                    out[(size_t)row * Dv + col]     = v0 + bias[col];
                    out[(size_t)row * Dv + col + 1] = v1 + bias[col + 1];
                }
            }
}

// ---------------------------------------------------------------------------
// Tensor-core causal flash attention. BM=128, BN=64, 8 warps.
// QK^T and PV single-pass fp16. Softmax: fp16x2 EX2 for P; row-sum l via
// ones-MMA (l = exact sum of the P actually used in PV).
// smem: Q 16KB; KV stages (Kh,Vh = 16KB) x2 at +16384.
// ---------------------------------------------------------------------------
#define KVSTG 16384
#define ATT_SMEM (16384 + 2 * KVSTG)   // 49152

__global__ __launch_bounds__(256, 2) void attn_tc()
{
    extern __shared__ char sm_[];
    uint32_t sb = smem_to_u32(sm_);
    const int tid = threadIdx.x, wid = tid >> 5, lane = tid & 31;
    const int qt = gridDim.x - 1 - blockIdx.x;   // big tiles first
    const int h = blockIdx.y, b = blockIdx.z;
    const int q0 = qt * 128;
    const size_t hb = (size_t)(b * Hv + h) * Sv * HDv;
    const __half *Qh = g_qh + hb, *Kh = g_kh + hb, *Vh = g_vh + hb;

    // Q tile via cp.async (128 rows x 8 units, fp16 single)
#pragma unroll
    for (int it = 0; it < 4; it++) {
        int idx = tid + it * 256;
        int row = idx >> 3, u = idx & 7;
        cp16(sb + swoff128(row, u), Qh + (size_t)(q0 + row) * HDv + u * 8);
    }
    CP_COMMIT();

    // Precomputed KV store offsets + source offsets
    const int kr0 = tid >> 3, ku0 = tid & 7;
    const int kr1 = (tid + 256) >> 3;
    const uint32_t kst0 = swoff128(kr0, ku0), kst1 = swoff128(kr1, ku0);
    const size_t ksrc0 = (size_t)kr0 * HDv + ku0 * 8;
    const size_t ksrc1 = (size_t)kr1 * HDv + ku0 * 8;

    auto issue_kv = [&](int kt, int stg) {
        uint32_t base = sb + 16384 + (uint32_t)stg * KVSTG;
        size_t adv = (size_t)kt * 64 * HDv;
        cp16(base + kst0,         Kh + adv + ksrc0);
        cp16(base + 8192 + kst0,  Vh + adv + ksrc0);
        cp16(base + kst1,         Kh + adv + ksrc1);
        cp16(base + 8192 + kst1,  Vh + adv + ksrc1);
        CP_COMMIT();
    };

    issue_kv(0, 0);

    const int lrow = lane & 15, lsel = lane >> 4, g = lane >> 2, t4 = lane & 3;

    // Precomputed ldmatrix offsets; k-step via XOR, V row-advance via +2048.
    const uint32_t q_off = swoff128(wid * 16 + lrow, lsel);
    uint32_t k_off[4], v_off[4];
#pragma unroll
    for (int p = 0; p < 4; p++) k_off[p] = swoff128(16 * p + lrow, lsel);
#pragma unroll
    for (int p2 = 0; p2 < 4; p2++) v_off[p2] = swoff128(lrow, 2 * p2 + lsel);

    float mreg[2] = {-1e30f, -1e30f}, lreg[2] = {0.f, 0.f};
    float o[8][4];
#pragma unroll
    for (int nt = 0; nt < 8; nt++)
#pragma unroll
        for (int k = 0; k < 4; k++) o[nt][k] = 0.f;

    const int gq0 = q0 + wid * 16 + g;
    const int gq1 = gq0 + 8;
    const int ntiles = 2 * qt + 2;

    for (int kt = 0; kt < ntiles; kt++) {
        CP_WAIT(0);
        __syncthreads();
        if (kt + 1 < ntiles) issue_kv(kt + 1, (kt + 1) & 1);

        uint32_t kvb = sb + 16384 + (uint32_t)(kt & 1) * KVSTG;
        const int k0r = kt * 64;

        // ---- S = Q K^T (single-pass fp16); scores already base-2 scaled ----
        float s[8][4];
#pragma unroll
        for (int nt = 0; nt < 8; nt++)
#pragma unroll
            for (int k = 0; k < 4; k++) s[nt][k] = 0.f;

#pragma unroll
        for (int ks = 0; ks < 4; ks++) {
            const uint32_t kso = (uint32_t)ks * 32u;
            uint32_t qh[4];
            ldm_x4(qh, sb + (q_off ^ kso));
            uint32_t kh[4][4];
#pragma unroll
            for (int p = 0; p < 4; p++)
                ldm_x4(kh[p], kvb + (k_off[p] ^ kso));
#pragma unroll
            for (int nt = 0; nt < 8; nt++) {
                int p = nt >> 1, q = nt & 1;
                mma_f16(s[nt], qh, kh[p][q], kh[p][q + 2]);
            }
        }

        // causal mask (only diagonal-region tiles)
        if (kt >= 2 * qt) {
#pragma unroll
            for (int nt = 0; nt < 8; nt++) {
                int c0 = k0r + 8 * nt + 2 * t4;
                if (c0 > gq0)     s[nt][0] = -1e30f;
                if (c0 + 1 > gq0) s[nt][1] = -1e30f;
                if (c0 > gq1)     s[nt][2] = -1e30f;
                if (c0 + 1 > gq1) s[nt][3] = -1e30f;
            }
        }

        // ---- online softmax (base 2) ----
        float rm0 = -1e30f, rm1 = -1e30f;
#pragma unroll
        for (int nt = 0; nt < 8; nt++) {
            rm0 = fmaxf(rm0, fmaxf(s[nt][0], s[nt][1]));
            rm1 = fmaxf(rm1, fmaxf(s[nt][2], s[nt][3]));
        }
        rm0 = fmaxf(rm0, __shfl_xor_sync(0xffffffffu, rm0, 1));
        rm0 = fmaxf(rm0, __shfl_xor_sync(0xffffffffu, rm0, 2));
        rm1 = fmaxf(rm1, __shfl_xor_sync(0xffffffffu, rm1, 1));
        rm1 = fmaxf(rm1, __shfl_xor_sync(0xffffffffu, rm1, 2));

        float nm0 = fmaxf(mreg[0], rm0), nm1 = fmaxf(mreg[1], rm1);
        float a0 = ex2(mreg[0] - nm0), a1 = ex2(mreg[1] - nm1);
        mreg[0] = nm0; mreg[1] = nm1;

        // P = 2^(s-nm) computed directly in fp16x2 (half the MUFU ops);
        // p16[nt][0] = rows gq0, p16[nt][1] = rows gq1
        uint32_t p16[8][2];
#pragma unroll
        for (int nt = 0; nt < 8; nt++) {
            p16[nt][0] = h2ex2(pack_f16x2(s[nt][0] - nm0, s[nt][1] - nm0));
            p16[nt][1] = h2ex2(pack_f16x2(s[nt][2] - nm1, s[nt][3] - nm1));
        }

#pragma unroll
        for (int nt = 0; nt < 8; nt++) {
            o[nt][0] *= a0; o[nt][1] *= a0;
            o[nt][2] *= a1; o[nt][3] *= a1;
        }

        // ---- O += P V; row-sum l via ones-MMA ----
        float lacc[4] = {0.f, 0.f, 0.f, 0.f};
#pragma unroll
        for (int ks = 0; ks < 4; ks++) {
            const uint32_t vko = (uint32_t)ks * 2048u;
            uint32_t ph[4];
            ph[0] = p16[2 * ks][0];
            ph[1] = p16[2 * ks][1];
            ph[2] = p16[2 * ks + 1][0];
            ph[3] = p16[2 * ks + 1][1];

            mma_f16(lacc, ph, ONES_H2, ONES_H2);   // row sums of P

            uint32_t vh[4][4];
#pragma unroll
            for (int p2 = 0; p2 < 4; p2++)
                ldm_x4_t(vh[p2], kvb + 8192 + v_off[p2] + vko);
#pragma unroll
            for (int nt = 0; nt < 8; nt++) {
                int p2 = nt >> 1, q = nt & 1;
                mma_f16(o[nt], ph, vh[p2][2 * q], vh[p2][2 * q + 1]);
            }
        }
        lreg[0] = lreg[0] * a0 + lacc[0];
        lreg[1] = lreg[1] * a1 + lacc[2];
    }

    // Epilogue: normalize, write ctx fp16 [B*S, D]
    float inv0 = 1.f / lreg[0], inv1 = 1.f / lreg[1];
#pragma unroll
    for (int nt = 0; nt < 8; nt++) {
        int col = h * HDv + 8 * nt + 2 * t4;
        size_t r0 = ((size_t)b * Sv + gq0) * Dv + col;
        size_t r1 = ((size_t)b * Sv + gq1) * Dv + col;
        *(uint32_t*)(g_ch + r0) = pack_f16x2(o[nt][0] * inv0, o[nt][1] * inv0);
        *(uint32_t*)(g_ch + r1) = pack_f16x2(o[nt][2] * inv1, o[nt][3] * inv1);
    }
}

// ---------------------------------------------------------------------------
extern "C" void kernel_launch(void* const* d_in, const int* in_sizes, int n_in,
                              void* d_out, int out_size)
{
    const float* X  = (const float*)d_in[0];
    const float* Wq = (const float*)d_in[1];
    const float* Wk = (const float*)d_in[2];
    const float* Wv = (const float*)d_in[3];
    const float* Wo = (const float*)d_in[4];
    const float* bo = (const float*)d_in[5];
    float* out = (float*)d_out;

    cudaFuncSetAttribute(gemm_tc,
                         cudaFuncAttributeMaxDynamicSharedMemorySize, GEMM_SMEM);
    cudaFuncSetAttribute(attn_tc,
                         cudaFuncAttributeMaxDynamicSharedMemorySize, ATT_SMEM);

    const int nX4 = Mv * Dv / 4;
    const int nW4 = Dv * Dv / 4;

    cvt_x_kernel<<<nX4 / 256, 256>>>((const float4*)X);
    cvt_w_kernel<<<dim3(nW4 / 256, 4), 256>>>(
        (const float4*)Wq, (const float4*)Wk, (const float4*)Wv, (const float4*)Wo);

    gemm_tc<<<dim3(Dv / 128, Mv / 128, 3), 256, GEMM_SMEM>>>(0, nullptr, nullptr);

    attn_tc<<<dim3(Sv / 128, Hv, Bv), 256, ATT_SMEM>>>();

    gemm_tc<<<dim3(Dv / 128, Mv / 128, 1), 256, GEMM_SMEM>>>(1, out, bo);
}